// round 2
// baseline (speedup 1.0000x reference)
#include <cuda_runtime.h>
#include <mma.h>

using namespace nvcuda;

// Problem constants
#define DM    1024          // d_model
#define HEADS 16
#define DK    64            // head dim
#define BB    4             // batch
#define SS    2048          // seq len
#define MTOT  (BB * SS)     // 8192 rows

// ---------------------------------------------------------------------------
// Scratch (device globals — no cudaMalloc allowed).
// NOTE: these symbols must ONLY be referenced from device code. Passing them
// as host-side kernel arguments passes the host shadow address (and on GB300
// with ATS the GPU silently reads host memory) — that was the R1 bug.
// ---------------------------------------------------------------------------
__device__ float g_Q[(size_t)MTOT * DM];     // (B,H,S,DK) layout
__device__ float g_K[(size_t)MTOT * DM];     // (B,H,S,DK) layout
__device__ float g_V[(size_t)MTOT * DM];     // (B,H,S,DK) layout
__device__ float g_attn[(size_t)MTOT * DM];  // (B,S,D) merged-head layout

// ---------------------------------------------------------------------------
// Helpers
// ---------------------------------------------------------------------------
template <typename Frag>
__device__ __forceinline__ void frag_to_tf32(Frag& f) {
#pragma unroll
    for (int i = 0; i < f.num_elements; i++)
        f.x[i] = wmma::__float_to_tf32(f.x[i]);
}

// ---------------------------------------------------------------------------
// GEMM: C = A @ W + bias.  A: (M x 1024), W: (1024 x 1024) row-major.
// Block tile 128x128, K-tile 16, 8 warps; each warp 32x64 (2x4 frags of 16x16).
// MODE 0: A = g_attn (device-resident), plain row-major write to Cplain.
// MODE 1: A = host-provided x; gridDim.z selects (Wq,Wk,Wv); write head-split
//         (B,H,S,DK) into g_Q/g_K/g_V (device-side symbol selection).
// ---------------------------------------------------------------------------
template <int MODE>
__global__ __launch_bounds__(256)
void gemm_tf32_kernel(const float* __restrict__ Ain,
                      const float* __restrict__ W0, const float* __restrict__ b0,
                      const float* __restrict__ W1, const float* __restrict__ b1,
                      const float* __restrict__ W2, const float* __restrict__ b2,
                      float* __restrict__ Cplain)
{
    const int z = blockIdx.z;
    const float* A    = (MODE == 0) ? (const float*)g_attn : Ain;
    const float* W    = (MODE == 0) ? W0 : (z == 0 ? W0 : (z == 1 ? W1 : W2));
    const float* bias = (MODE == 0) ? b0 : (z == 0 ? b0 : (z == 1 ? b1 : b2));
    float* C = (MODE == 0) ? Cplain : (z == 0 ? g_Q : (z == 1 ? g_K : g_V));

    __shared__ float As[128][20];    // padded vs bank conflicts
    __shared__ float Bs[16][136];
    __shared__ float epi[8][16 * 16];

    const int tid  = threadIdx.x;
    const int warp = tid >> 5;
    const int lane = tid & 31;
    const int wm   = warp >> 1;   // 0..3  (rows of warp grid)
    const int wn   = warp & 1;    // 0..1  (cols of warp grid)
    const int m0   = blockIdx.y * 128;
    const int n0   = blockIdx.x * 128;

    wmma::fragment<wmma::accumulator, 16, 16, 8, float> acc[2][4];
#pragma unroll
    for (int im = 0; im < 2; im++)
#pragma unroll
        for (int in = 0; in < 4; in++)
            wmma::fill_fragment(acc[im][in], 0.0f);

    for (int k0 = 0; k0 < DM; k0 += 16) {
        // --- load A tile 128x16 (512 float4, 2 per thread), convert to tf32 ---
#pragma unroll
        for (int r = 0; r < 2; r++) {
            int id  = tid + r * 256;
            int row = id >> 2;
            int c4  = (id & 3) * 4;
            float4 v = *(const float4*)&A[(size_t)(m0 + row) * DM + k0 + c4];
            As[row][c4 + 0] = wmma::__float_to_tf32(v.x);
            As[row][c4 + 1] = wmma::__float_to_tf32(v.y);
            As[row][c4 + 2] = wmma::__float_to_tf32(v.z);
            As[row][c4 + 3] = wmma::__float_to_tf32(v.w);
        }
        // --- load B tile 16x128 ---
#pragma unroll
        for (int r = 0; r < 2; r++) {
            int id  = tid + r * 256;
            int row = id >> 5;
            int c4  = (id & 31) * 4;
            float4 v = *(const float4*)&W[(size_t)(k0 + row) * DM + n0 + c4];
            Bs[row][c4 + 0] = wmma::__float_to_tf32(v.x);
            Bs[row][c4 + 1] = wmma::__float_to_tf32(v.y);
            Bs[row][c4 + 2] = wmma::__float_to_tf32(v.z);
            Bs[row][c4 + 3] = wmma::__float_to_tf32(v.w);
        }
        __syncthreads();

#pragma unroll
        for (int ks = 0; ks < 2; ks++) {
            wmma::fragment<wmma::matrix_a, 16, 16, 8, wmma::precision::tf32, wmma::row_major> af[2];
            wmma::fragment<wmma::matrix_b, 16, 16, 8, wmma::precision::tf32, wmma::row_major> bf[4];
#pragma unroll
            for (int im = 0; im < 2; im++)
                wmma::load_matrix_sync(af[im], &As[wm * 32 + im * 16][ks * 8], 20);
#pragma unroll
            for (int in = 0; in < 4; in++)
                wmma::load_matrix_sync(bf[in], &Bs[ks * 8][wn * 64 + in * 16], 136);
#pragma unroll
            for (int im = 0; im < 2; im++)
#pragma unroll
                for (int in = 0; in < 4; in++)
                    wmma::mma_sync(acc[im][in], af[im], bf[in], acc[im][in]);
        }
        __syncthreads();
    }

    // --- epilogue: frag -> smem -> global (+bias, layout map) ---
#pragma unroll
    for (int im = 0; im < 2; im++) {
#pragma unroll
        for (int in = 0; in < 4; in++) {
            wmma::store_matrix_sync(epi[warp], acc[im][in], 16, wmma::mem_row_major);
            __syncwarp();
#pragma unroll
            for (int i = 0; i < 8; i++) {
                int v = lane * 8 + i;
                int r = v >> 4, c = v & 15;
                int gm = m0 + wm * 32 + im * 16 + r;
                int gn = n0 + wn * 64 + in * 16 + c;
                float val = epi[warp][v] + bias[gn];
                if (MODE == 0) {
                    C[(size_t)gm * DM + gn] = val;
                } else {
                    int b = gm >> 11, s = gm & 2047;   // M = b*2048 + s
                    int h = gn >> 6,  d = gn & 63;     // N = h*64 + d
                    C[(((size_t)(b * HEADS + h)) * SS + s) * DK + d] = val;
                }
            }
            __syncwarp();
        }
    }
}

// ---------------------------------------------------------------------------
// Flash attention: one block per (b*h, 64-row q tile). 8 warps.
// Q held in tf32 A-fragments for the whole kernel. K/V B-fragments loaded
// directly from global (L1 resident within block). Scores staged through SMEM
// for online softmax; O accumulator in SMEM, rescaled per K-tile.
// ---------------------------------------------------------------------------
__global__ __launch_bounds__(256)
void flash_attn_kernel()
{
    __shared__ float Ss[64][68];
    __shared__ float Os[64][68];
    __shared__ float m_s[64];
    __shared__ float l_s[64];

    const int tid  = threadIdx.x;
    const int warp = tid >> 5;
    const int wm   = warp >> 1;   // 0..3: 16-row band of the 64-row tile
    const int wn   = warp & 1;    // 0..1: 32-col band
    const int qt   = blockIdx.x;  // 0..31
    const int bh   = blockIdx.y;  // 0..63

    const float* Qb = g_Q + (size_t)bh * SS * DK;
    const float* Kb = g_K + (size_t)bh * SS * DK;
    const float* Vb = g_V + (size_t)bh * SS * DK;

    for (int i = tid; i < 64 * 68; i += 256) (&Os[0][0])[i] = 0.0f;
    if (tid < 64) { m_s[tid] = -1e30f; l_s[tid] = 0.0f; }
    __syncthreads();

    // preload this warp's 16 Q rows as 8 tf32 A fragments (k = 0..63)
    wmma::fragment<wmma::matrix_a, 16, 16, 8, wmma::precision::tf32, wmma::row_major> qf[8];
#pragma unroll
    for (int kk = 0; kk < 8; kk++) {
        wmma::load_matrix_sync(qf[kk], Qb + (size_t)(qt * 64 + wm * 16) * DK + kk * 8, DK);
        frag_to_tf32(qf[kk]);
    }

    const int   r   = tid >> 2;     // row 0..63 (4 threads per row)
    const int   q4  = tid & 3;      // quarter of the row (16 cols)
    const float sm_scale = 0.125f;  // 1/sqrt(64)

    for (int jt = 0; jt < SS / 64; jt++) {
        // ---- scores tile: S = Q @ K^T ----
        wmma::fragment<wmma::accumulator, 16, 16, 8, float> sacc[2];
        wmma::fill_fragment(sacc[0], 0.0f);
        wmma::fill_fragment(sacc[1], 0.0f);
#pragma unroll
        for (int kk = 0; kk < 8; kk++) {
#pragma unroll
            for (int in = 0; in < 2; in++) {
                wmma::fragment<wmma::matrix_b, 16, 16, 8, wmma::precision::tf32, wmma::col_major> kf;
                wmma::load_matrix_sync(kf, Kb + (size_t)(jt * 64 + wn * 32 + in * 16) * DK + kk * 8, DK);
                frag_to_tf32(kf);
                wmma::mma_sync(sacc[in], qf[kk], kf, sacc[in]);
            }
        }
#pragma unroll
        for (int in = 0; in < 2; in++)
            wmma::store_matrix_sync(&Ss[wm * 16][wn * 32 + in * 16], sacc[in], 68, wmma::mem_row_major);
        __syncthreads();

        // ---- online softmax (4 threads per row) ----
        {
            float mo = m_s[r], lo = l_s[r];
            float vals[16];
            float mx = -1e30f;
#pragma unroll
            for (int i = 0; i < 16; i++) {
                vals[i] = Ss[r][q4 * 16 + i] * sm_scale;
                mx = fmaxf(mx, vals[i]);
            }
            mx = fmaxf(mx, __shfl_xor_sync(0xffffffffu, mx, 1));
            mx = fmaxf(mx, __shfl_xor_sync(0xffffffffu, mx, 2));
            float mn = fmaxf(mo, mx);
            float sc = __expf(mo - mn);
            float sum = 0.0f;
#pragma unroll
            for (int i = 0; i < 16; i++) {
                float p = __expf(vals[i] - mn);
                sum += p;
                Ss[r][q4 * 16 + i] = p;
            }
            sum += __shfl_xor_sync(0xffffffffu, sum, 1);
            sum += __shfl_xor_sync(0xffffffffu, sum, 2);
#pragma unroll
            for (int i = 0; i < 16; i++)
                Os[r][q4 * 16 + i] *= sc;
            if (q4 == 0) {
                m_s[r] = mn;
                l_s[r] = lo * sc + sum;
            }
        }
        __syncthreads();

        // ---- O += P @ V ----
        wmma::fragment<wmma::accumulator, 16, 16, 8, float> oacc[2];
#pragma unroll
        for (int in = 0; in < 2; in++)
            wmma::load_matrix_sync(oacc[in], &Os[wm * 16][wn * 32 + in * 16], 68, wmma::mem_row_major);
#pragma unroll
        for (int kk = 0; kk < 8; kk++) {
            wmma::fragment<wmma::matrix_a, 16, 16, 8, wmma::precision::tf32, wmma::row_major> pf;
            wmma::load_matrix_sync(pf, &Ss[wm * 16][kk * 8], 68);
            frag_to_tf32(pf);
#pragma unroll
            for (int in = 0; in < 2; in++) {
                wmma::fragment<wmma::matrix_b, 16, 16, 8, wmma::precision::tf32, wmma::row_major> vf;
                wmma::load_matrix_sync(vf, Vb + (size_t)(jt * 64 + kk * 8) * DK + wn * 32 + in * 16, DK);
                frag_to_tf32(vf);
                wmma::mma_sync(oacc[in], pf, vf, oacc[in]);
            }
        }
#pragma unroll
        for (int in = 0; in < 2; in++)
            wmma::store_matrix_sync(&Os[wm * 16][wn * 32 + in * 16], oacc[in], 68, wmma::mem_row_major);
        __syncthreads();
    }

    // ---- normalize + write merged-head layout (B,S,D) ----
    {
        int b = bh >> 4, h = bh & 15;
        int s = qt * 64 + r;
        float inv = 1.0f / l_s[r];
#pragma unroll
        for (int i = 0; i < 16; i++) {
            g_attn[((size_t)(b * SS + s)) * DM + h * DK + q4 * 16 + i] = Os[r][q4 * 16 + i] * inv;
        }
    }
}

// ---------------------------------------------------------------------------
// Launcher. Inputs (metadata order): x, Wq, bq, Wk, bk, Wv, bv, Wo, bo
// ---------------------------------------------------------------------------
extern "C" void kernel_launch(void* const* d_in, const int* in_sizes, int n_in,
                              void* d_out, int out_size)
{
    const float* x  = (const float*)d_in[0];
    const float* Wq = (const float*)d_in[1];
    const float* bq = (const float*)d_in[2];
    const float* Wk = (const float*)d_in[3];
    const float* bk = (const float*)d_in[4];
    const float* Wv = (const float*)d_in[5];
    const float* bv = (const float*)d_in[6];
    const float* Wo = (const float*)d_in[7];
    const float* bo = (const float*)d_in[8];
    float* out = (float*)d_out;

    // 1) QKV projections (z = 0,1,2 -> Q,K,V), head-split epilogue
    {
        dim3 grid(DM / 128, MTOT / 128, 3);
        gemm_tf32_kernel<1><<<grid, 256>>>(x, Wq, bq, Wk, bk, Wv, bv, nullptr);
    }
    // 2) flash attention
    {
        dim3 grid(SS / 64, BB * HEADS);
        flash_attn_kernel<<<grid, 256>>>();
    }
    // 3) output projection (A operand = g_attn, bound inside the kernel)
    {
        dim3 grid(DM / 128, MTOT / 128, 1);
        gemm_tf32_kernel<0><<<grid, 256>>>(nullptr, Wo, bo, nullptr, nullptr, nullptr, nullptr, out);
    }
}

// round 3
// speedup vs baseline: 1.2381x; 1.2381x over previous
#include <cuda_runtime.h>
#include <mma.h>

using namespace nvcuda;

// Problem constants
#define DM    1024          // d_model
#define HEADS 16
#define DK    64            // head dim
#define BB    4             // batch
#define SS    2048          // seq len
#define MTOT  (BB * SS)     // 8192 rows

// ---------------------------------------------------------------------------
// Scratch (device globals — no cudaMalloc allowed).
// Only referenced from device code (host-shadow aliasing was the R1 bug).
// ---------------------------------------------------------------------------
__device__ float g_Q[(size_t)MTOT * DM];     // (B,H,S,DK) layout
__device__ float g_K[(size_t)MTOT * DM];     // (B,H,S,DK) layout
__device__ float g_V[(size_t)MTOT * DM];     // (B,H,S,DK) layout
__device__ float g_attn[(size_t)MTOT * DM];  // (B,S,D) merged-head layout

// ---------------------------------------------------------------------------
// Helpers
// ---------------------------------------------------------------------------
template <typename Frag>
__device__ __forceinline__ void frag_to_tf32(Frag& f) {
#pragma unroll
    for (int i = 0; i < f.num_elements; i++)
        f.x[i] = wmma::__float_to_tf32(f.x[i]);
}

// ---------------------------------------------------------------------------
// GEMM: C = A @ W + bias. (unchanged from R2 — known good)
// ---------------------------------------------------------------------------
template <int MODE>
__global__ __launch_bounds__(256)
void gemm_tf32_kernel(const float* __restrict__ Ain,
                      const float* __restrict__ W0, const float* __restrict__ b0,
                      const float* __restrict__ W1, const float* __restrict__ b1,
                      const float* __restrict__ W2, const float* __restrict__ b2,
                      float* __restrict__ Cplain)
{
    const int z = blockIdx.z;
    const float* A    = (MODE == 0) ? (const float*)g_attn : Ain;
    const float* W    = (MODE == 0) ? W0 : (z == 0 ? W0 : (z == 1 ? W1 : W2));
    const float* bias = (MODE == 0) ? b0 : (z == 0 ? b0 : (z == 1 ? b1 : b2));
    float* C = (MODE == 0) ? Cplain : (z == 0 ? g_Q : (z == 1 ? g_K : g_V));

    __shared__ float As[128][20];
    __shared__ float Bs[16][136];
    __shared__ float epi[8][16 * 16];

    const int tid  = threadIdx.x;
    const int warp = tid >> 5;
    const int lane = tid & 31;
    const int wm   = warp >> 1;
    const int wn   = warp & 1;
    const int m0   = blockIdx.y * 128;
    const int n0   = blockIdx.x * 128;

    wmma::fragment<wmma::accumulator, 16, 16, 8, float> acc[2][4];
#pragma unroll
    for (int im = 0; im < 2; im++)
#pragma unroll
        for (int in = 0; in < 4; in++)
            wmma::fill_fragment(acc[im][in], 0.0f);

    for (int k0 = 0; k0 < DM; k0 += 16) {
#pragma unroll
        for (int r = 0; r < 2; r++) {
            int id  = tid + r * 256;
            int row = id >> 2;
            int c4  = (id & 3) * 4;
            float4 v = *(const float4*)&A[(size_t)(m0 + row) * DM + k0 + c4];
            As[row][c4 + 0] = wmma::__float_to_tf32(v.x);
            As[row][c4 + 1] = wmma::__float_to_tf32(v.y);
            As[row][c4 + 2] = wmma::__float_to_tf32(v.z);
            As[row][c4 + 3] = wmma::__float_to_tf32(v.w);
        }
#pragma unroll
        for (int r = 0; r < 2; r++) {
            int id  = tid + r * 256;
            int row = id >> 5;
            int c4  = (id & 31) * 4;
            float4 v = *(const float4*)&W[(size_t)(k0 + row) * DM + n0 + c4];
            Bs[row][c4 + 0] = wmma::__float_to_tf32(v.x);
            Bs[row][c4 + 1] = wmma::__float_to_tf32(v.y);
            Bs[row][c4 + 2] = wmma::__float_to_tf32(v.z);
            Bs[row][c4 + 3] = wmma::__float_to_tf32(v.w);
        }
        __syncthreads();

#pragma unroll
        for (int ks = 0; ks < 2; ks++) {
            wmma::fragment<wmma::matrix_a, 16, 16, 8, wmma::precision::tf32, wmma::row_major> af[2];
            wmma::fragment<wmma::matrix_b, 16, 16, 8, wmma::precision::tf32, wmma::row_major> bf[4];
#pragma unroll
            for (int im = 0; im < 2; im++)
                wmma::load_matrix_sync(af[im], &As[wm * 32 + im * 16][ks * 8], 20);
#pragma unroll
            for (int in = 0; in < 4; in++)
                wmma::load_matrix_sync(bf[in], &Bs[ks * 8][wn * 64 + in * 16], 136);
#pragma unroll
            for (int im = 0; im < 2; im++)
#pragma unroll
                for (int in = 0; in < 4; in++)
                    wmma::mma_sync(acc[im][in], af[im], bf[in], acc[im][in]);
        }
        __syncthreads();
    }

#pragma unroll
    for (int im = 0; im < 2; im++) {
#pragma unroll
        for (int in = 0; in < 4; in++) {
            wmma::store_matrix_sync(epi[warp], acc[im][in], 16, wmma::mem_row_major);
            __syncwarp();
#pragma unroll
            for (int i = 0; i < 8; i++) {
                int v = lane * 8 + i;
                int r = v >> 4, c = v & 15;
                int gm = m0 + wm * 32 + im * 16 + r;
                int gn = n0 + wn * 64 + in * 16 + c;
                float val = epi[warp][v] + bias[gn];
                if (MODE == 0) {
                    C[(size_t)gm * DM + gn] = val;
                } else {
                    int b = gm >> 11, s = gm & 2047;
                    int h = gn >> 6,  d = gn & 63;
                    C[(((size_t)(b * HEADS + h)) * SS + s) * DK + d] = val;
                }
            }
            __syncwarp();
        }
    }
}

// ---------------------------------------------------------------------------
// Flash attention v2: one block per (b*h, 64-row q tile). 8 warps, dyn SMEM.
// K/V tiles staged in SMEM once per 64-key iteration (float4 loads, tf32
// conversion at store time). All fragments come from SMEM. Q pre-scaled by
// 1/sqrt(dk) at load.
// SMEM layout (floats): Ks[64][68] | Vs[64][68] | Ss[64][68] | Os[64][68]
//                       | m_s[64] | l_s[64]
// ---------------------------------------------------------------------------
#define LDP 68
#define TILE_F (64 * LDP)

__global__ __launch_bounds__(256)
void flash_attn_kernel()
{
    extern __shared__ float sm[];
    float* Ks  = sm;
    float* Vs  = sm + TILE_F;
    float* Ss  = sm + 2 * TILE_F;
    float* Os  = sm + 3 * TILE_F;
    float* m_s = sm + 4 * TILE_F;
    float* l_s = m_s + 64;

    const int tid  = threadIdx.x;
    const int warp = tid >> 5;
    const int wm   = warp >> 1;   // 0..3: 16-row band of the 64-row q tile
    const int wn   = warp & 1;    // 0..1: 32-col band of keys
    const int qt   = blockIdx.x;  // 0..31
    const int bh   = blockIdx.y;  // 0..63

    const float* Qb = g_Q + (size_t)bh * SS * DK;
    const float* Kb = g_K + (size_t)bh * SS * DK;
    const float* Vb = g_V + (size_t)bh * SS * DK;

    for (int i = tid; i < TILE_F; i += 256) Os[i] = 0.0f;
    if (tid < 64) { m_s[tid] = -1e30f; l_s[tid] = 0.0f; }

    // preload this warp's 16 Q rows as 8 tf32 A fragments, pre-scaled by 1/8
    wmma::fragment<wmma::matrix_a, 16, 16, 8, wmma::precision::tf32, wmma::row_major> qf[8];
#pragma unroll
    for (int kk = 0; kk < 8; kk++) {
        wmma::load_matrix_sync(qf[kk], Qb + (size_t)(qt * 64 + wm * 16) * DK + kk * 8, DK);
#pragma unroll
        for (int i = 0; i < qf[kk].num_elements; i++)
            qf[kk].x[i] = wmma::__float_to_tf32(qf[kk].x[i] * 0.125f);
    }
    __syncthreads();

    const int r  = tid >> 2;   // row 0..63 (4 threads per row)
    const int q4 = tid & 3;    // 16-col quarter

    // K/V staging indices: 1024 float4 per tile, 256 threads -> 4 each
    const int ld_row = tid >> 2;          // 0..63
    const int ld_c4  = (tid & 3) * 4;     // 0,4,8,12 -> +16 per step

    for (int jt = 0; jt < SS / 64; jt++) {
        // ---- stage K, V tiles into SMEM (tf32-converted) ----
        const float* Kt = Kb + (size_t)(jt * 64) * DK;
        const float* Vt = Vb + (size_t)(jt * 64) * DK;
#pragma unroll
        for (int p = 0; p < 4; p++) {
            int c = ld_c4 + p * 16;
            float4 kv = *(const float4*)&Kt[(size_t)ld_row * DK + c];
            float4 vv = *(const float4*)&Vt[(size_t)ld_row * DK + c];
            float* kd = &Ks[ld_row * LDP + c];
            float* vd = &Vs[ld_row * LDP + c];
            kd[0] = wmma::__float_to_tf32(kv.x);
            kd[1] = wmma::__float_to_tf32(kv.y);
            kd[2] = wmma::__float_to_tf32(kv.z);
            kd[3] = wmma::__float_to_tf32(kv.w);
            vd[0] = wmma::__float_to_tf32(vv.x);
            vd[1] = wmma::__float_to_tf32(vv.y);
            vd[2] = wmma::__float_to_tf32(vv.z);
            vd[3] = wmma::__float_to_tf32(vv.w);
        }
        __syncthreads();

        // ---- scores tile: S = (Q/8) @ K^T ----
        wmma::fragment<wmma::accumulator, 16, 16, 8, float> sacc[2];
        wmma::fill_fragment(sacc[0], 0.0f);
        wmma::fill_fragment(sacc[1], 0.0f);
#pragma unroll
        for (int kk = 0; kk < 8; kk++) {
#pragma unroll
            for (int in = 0; in < 2; in++) {
                wmma::fragment<wmma::matrix_b, 16, 16, 8, wmma::precision::tf32, wmma::col_major> kf;
                wmma::load_matrix_sync(kf, &Ks[(wn * 32 + in * 16) * LDP + kk * 8], LDP);
                wmma::mma_sync(sacc[in], qf[kk], kf, sacc[in]);
            }
        }
#pragma unroll
        for (int in = 0; in < 2; in++)
            wmma::store_matrix_sync(&Ss[(wm * 16) * LDP + wn * 32 + in * 16], sacc[in], LDP, wmma::mem_row_major);
        __syncthreads();

        // ---- online softmax (4 threads per row; scores already scaled) ----
        {
            float mo = m_s[r], lo = l_s[r];
            float vals[16];
            float mx = -1e30f;
#pragma unroll
            for (int i = 0; i < 16; i++) {
                vals[i] = Ss[r * LDP + q4 * 16 + i];
                mx = fmaxf(mx, vals[i]);
            }
            mx = fmaxf(mx, __shfl_xor_sync(0xffffffffu, mx, 1));
            mx = fmaxf(mx, __shfl_xor_sync(0xffffffffu, mx, 2));
            float mn = fmaxf(mo, mx);
            float sc = __expf(mo - mn);
            float sum = 0.0f;
#pragma unroll
            for (int i = 0; i < 16; i++) {
                float p = __expf(vals[i] - mn);
                sum += p;
                Ss[r * LDP + q4 * 16 + i] = p;
            }
            sum += __shfl_xor_sync(0xffffffffu, sum, 1);
            sum += __shfl_xor_sync(0xffffffffu, sum, 2);
#pragma unroll
            for (int i = 0; i < 16; i++)
                Os[r * LDP + q4 * 16 + i] *= sc;
            if (q4 == 0) {
                m_s[r] = mn;
                l_s[r] = lo * sc + sum;
            }
        }
        __syncthreads();

        // ---- O += P @ V (P and V both in SMEM) ----
        wmma::fragment<wmma::accumulator, 16, 16, 8, float> oacc[2];
#pragma unroll
        for (int in = 0; in < 2; in++)
            wmma::load_matrix_sync(oacc[in], &Os[(wm * 16) * LDP + wn * 32 + in * 16], LDP, wmma::mem_row_major);
#pragma unroll
        for (int kk = 0; kk < 8; kk++) {
            wmma::fragment<wmma::matrix_a, 16, 16, 8, wmma::precision::tf32, wmma::row_major> pf;
            wmma::load_matrix_sync(pf, &Ss[(wm * 16) * LDP + kk * 8], LDP);
            frag_to_tf32(pf);
#pragma unroll
            for (int in = 0; in < 2; in++) {
                wmma::fragment<wmma::matrix_b, 16, 16, 8, wmma::precision::tf32, wmma::row_major> vf;
                wmma::load_matrix_sync(vf, &Vs[(kk * 8) * LDP + wn * 32 + in * 16], LDP);
                wmma::mma_sync(oacc[in], pf, vf, oacc[in]);
            }
        }
#pragma unroll
        for (int in = 0; in < 2; in++)
            wmma::store_matrix_sync(&Os[(wm * 16) * LDP + wn * 32 + in * 16], oacc[in], LDP, wmma::mem_row_major);
        __syncthreads();
    }

    // ---- normalize + write merged-head layout (B,S,D) ----
    {
        int b = bh >> 4, h = bh & 15;
        int s = qt * 64 + r;
        float inv = 1.0f / l_s[r];
#pragma unroll
        for (int i = 0; i < 16; i++) {
            g_attn[((size_t)(b * SS + s)) * DM + h * DK + q4 * 16 + i] = Os[r * LDP + q4 * 16 + i] * inv;
        }
    }
}

#define FLASH_SMEM_BYTES ((4 * TILE_F + 128) * (int)sizeof(float))

// ---------------------------------------------------------------------------
// Launcher. Inputs (metadata order): x, Wq, bq, Wk, bk, Wv, bv, Wo, bo
// ---------------------------------------------------------------------------
extern "C" void kernel_launch(void* const* d_in, const int* in_sizes, int n_in,
                              void* d_out, int out_size)
{
    const float* x  = (const float*)d_in[0];
    const float* Wq = (const float*)d_in[1];
    const float* bq = (const float*)d_in[2];
    const float* Wk = (const float*)d_in[3];
    const float* bk = (const float*)d_in[4];
    const float* Wv = (const float*)d_in[5];
    const float* bv = (const float*)d_in[6];
    const float* Wo = (const float*)d_in[7];
    const float* bo = (const float*)d_in[8];
    float* out = (float*)d_out;

    cudaFuncSetAttribute(flash_attn_kernel,
                         cudaFuncAttributeMaxDynamicSharedMemorySize, FLASH_SMEM_BYTES);

    // 1) QKV projections
    {
        dim3 grid(DM / 128, MTOT / 128, 3);
        gemm_tf32_kernel<1><<<grid, 256>>>(x, Wq, bq, Wk, bk, Wv, bv, nullptr);
    }
    // 2) flash attention
    {
        dim3 grid(SS / 64, BB * HEADS);
        flash_attn_kernel<<<grid, 256, FLASH_SMEM_BYTES>>>();
    }
    // 3) output projection
    {
        dim3 grid(DM / 128, MTOT / 128, 1);
        gemm_tf32_kernel<0><<<grid, 256>>>(nullptr, Wo, bo, nullptr, nullptr, nullptr, nullptr, out);
    }
}

// round 4
// speedup vs baseline: 2.0511x; 1.6566x over previous
#include <cuda_runtime.h>
#include <mma.h>
#include <cstdint>

using namespace nvcuda;

// Problem constants
#define DM    1024          // d_model
#define HEADS 16
#define DK    64            // head dim
#define BB    4             // batch
#define SS    2048          // seq len
#define MTOT  (BB * SS)     // 8192 rows

// ---------------------------------------------------------------------------
// Scratch (device globals — no cudaMalloc allowed).
// Only referenced from device code (host-shadow aliasing was the R1 bug).
// ---------------------------------------------------------------------------
__device__ float g_Q[(size_t)MTOT * DM];     // (B,H,S,DK) layout
__device__ float g_K[(size_t)MTOT * DM];     // (B,H,S,DK) layout
__device__ float g_V[(size_t)MTOT * DM];     // (B,H,S,DK) layout
__device__ float g_attn[(size_t)MTOT * DM];  // (B,S,D) merged-head layout

// ---------------------------------------------------------------------------
// Helpers
// ---------------------------------------------------------------------------
__device__ __forceinline__ uint32_t f2tf32(float x) {
    uint32_t u;
    asm("cvt.rna.tf32.f32 %0, %1;" : "=r"(u) : "f"(x));
    return u;
}

// mma.m16n8k8 tf32: C(16x8,f32) += A(16x8,row) * B(8x8,col)
__device__ __forceinline__ void mma_tf32(float c[4], const uint32_t a[4],
                                         uint32_t b0, uint32_t b1) {
    asm volatile(
        "mma.sync.aligned.m16n8k8.row.col.f32.tf32.tf32.f32 "
        "{%0,%1,%2,%3}, {%4,%5,%6,%7}, {%8,%9}, {%0,%1,%2,%3};"
        : "+f"(c[0]), "+f"(c[1]), "+f"(c[2]), "+f"(c[3])
        : "r"(a[0]), "r"(a[1]), "r"(a[2]), "r"(a[3]), "r"(b0), "r"(b1));
}

// ---------------------------------------------------------------------------
// GEMM: C = A @ W + bias. (unchanged — known good)
// ---------------------------------------------------------------------------
template <int MODE>
__global__ __launch_bounds__(256)
void gemm_tf32_kernel(const float* __restrict__ Ain,
                      const float* __restrict__ W0, const float* __restrict__ b0,
                      const float* __restrict__ W1, const float* __restrict__ b1,
                      const float* __restrict__ W2, const float* __restrict__ b2,
                      float* __restrict__ Cplain)
{
    const int z = blockIdx.z;
    const float* A    = (MODE == 0) ? (const float*)g_attn : Ain;
    const float* W    = (MODE == 0) ? W0 : (z == 0 ? W0 : (z == 1 ? W1 : W2));
    const float* bias = (MODE == 0) ? b0 : (z == 0 ? b0 : (z == 1 ? b1 : b2));
    float* C = (MODE == 0) ? Cplain : (z == 0 ? g_Q : (z == 1 ? g_K : g_V));

    __shared__ float As[128][20];
    __shared__ float Bs[16][136];
    __shared__ float epi[8][16 * 16];

    const int tid  = threadIdx.x;
    const int warp = tid >> 5;
    const int lane = tid & 31;
    const int wm   = warp >> 1;
    const int wn   = warp & 1;
    const int m0   = blockIdx.y * 128;
    const int n0   = blockIdx.x * 128;

    wmma::fragment<wmma::accumulator, 16, 16, 8, float> acc[2][4];
#pragma unroll
    for (int im = 0; im < 2; im++)
#pragma unroll
        for (int in = 0; in < 4; in++)
            wmma::fill_fragment(acc[im][in], 0.0f);

    for (int k0 = 0; k0 < DM; k0 += 16) {
#pragma unroll
        for (int r = 0; r < 2; r++) {
            int id  = tid + r * 256;
            int row = id >> 2;
            int c4  = (id & 3) * 4;
            float4 v = *(const float4*)&A[(size_t)(m0 + row) * DM + k0 + c4];
            As[row][c4 + 0] = wmma::__float_to_tf32(v.x);
            As[row][c4 + 1] = wmma::__float_to_tf32(v.y);
            As[row][c4 + 2] = wmma::__float_to_tf32(v.z);
            As[row][c4 + 3] = wmma::__float_to_tf32(v.w);
        }
#pragma unroll
        for (int r = 0; r < 2; r++) {
            int id  = tid + r * 256;
            int row = id >> 5;
            int c4  = (id & 31) * 4;
            float4 v = *(const float4*)&W[(size_t)(k0 + row) * DM + n0 + c4];
            Bs[row][c4 + 0] = wmma::__float_to_tf32(v.x);
            Bs[row][c4 + 1] = wmma::__float_to_tf32(v.y);
            Bs[row][c4 + 2] = wmma::__float_to_tf32(v.z);
            Bs[row][c4 + 3] = wmma::__float_to_tf32(v.w);
        }
        __syncthreads();

#pragma unroll
        for (int ks = 0; ks < 2; ks++) {
            wmma::fragment<wmma::matrix_a, 16, 16, 8, wmma::precision::tf32, wmma::row_major> af[2];
            wmma::fragment<wmma::matrix_b, 16, 16, 8, wmma::precision::tf32, wmma::row_major> bf[4];
#pragma unroll
            for (int im = 0; im < 2; im++)
                wmma::load_matrix_sync(af[im], &As[wm * 32 + im * 16][ks * 8], 20);
#pragma unroll
            for (int in = 0; in < 4; in++)
                wmma::load_matrix_sync(bf[in], &Bs[ks * 8][wn * 64 + in * 16], 136);
#pragma unroll
            for (int im = 0; im < 2; im++)
#pragma unroll
                for (int in = 0; in < 4; in++)
                    wmma::mma_sync(acc[im][in], af[im], bf[in], acc[im][in]);
        }
        __syncthreads();
    }

#pragma unroll
    for (int im = 0; im < 2; im++) {
#pragma unroll
        for (int in = 0; in < 4; in++) {
            wmma::store_matrix_sync(epi[warp], acc[im][in], 16, wmma::mem_row_major);
            __syncwarp();
#pragma unroll
            for (int i = 0; i < 8; i++) {
                int v = lane * 8 + i;
                int r = v >> 4, c = v & 15;
                int gm = m0 + wm * 32 + im * 16 + r;
                int gn = n0 + wn * 64 + in * 16 + c;
                float val = epi[warp][v] + bias[gn];
                if (MODE == 0) {
                    C[(size_t)gm * DM + gn] = val;
                } else {
                    int b = gm >> 11, s = gm & 2047;
                    int h = gn >> 6,  d = gn & 63;
                    C[(((size_t)(b * HEADS + h)) * SS + s) * DK + d] = val;
                }
            }
            __syncwarp();
        }
    }
}

// ---------------------------------------------------------------------------
// Flash attention v3 — FlashAttention-2 style, raw PTX mma.m16n8k8.tf32.
// Block: 128 q rows, 8 warps, each warp owns 16 rows x full dk=64.
// Q, S, O live in registers; softmax on register fragments (2 shfl per
// reduction); O rescale in registers. P transits per-warp SMEM (C-frag ->
// A-frag layout change) guarded by __syncwarp only.
// KV tile: 64 keys staged in SMEM per iteration (K row-major, V transposed),
// tf32-converted at store. LDK=68 makes frag loads bank-conflict-free.
// ---------------------------------------------------------------------------
#define LDK 68
#define FLASH_SMEM_BYTES ((2 * 64 * LDK + 128 * LDK) * (int)sizeof(float))

__global__ __launch_bounds__(256, 2)
void flash_attn_kernel()
{
    extern __shared__ float smf[];
    float* Ks  = smf;                 // [64 keys][LDK] (dk-major rows)
    float* VsT = smf + 64 * LDK;      // [64 dk][LDK]   (transposed: key-major rows)
    float* Ps  = smf + 2 * 64 * LDK;  // [128 rows][LDK]

    const int tid  = threadIdx.x;
    const int warp = tid >> 5;
    const int lane = tid & 31;
    const int gr   = lane >> 2;       // 0..7
    const int gc   = lane & 3;        // 0..3
    const int qt   = blockIdx.x;      // 0..15
    const int bh   = blockIdx.y;      // 0..63

    const float* Qb = g_Q + (size_t)bh * SS * DK;
    const float* Kb = g_K + (size_t)bh * SS * DK;
    const float* Vb = g_V + (size_t)bh * SS * DK;

    const int qrow = qt * 128 + warp * 16;   // this warp's 16 q rows

    // ---- Q as A-fragments (8 k-steps x 4 regs), pre-scaled by 1/sqrt(dk) ----
    uint32_t qa[8][4];
#pragma unroll
    for (int kk = 0; kk < 8; kk++) {
        const float* q0 = Qb + (size_t)(qrow + gr)     * DK + kk * 8 + gc;
        const float* q1 = Qb + (size_t)(qrow + gr + 8) * DK + kk * 8 + gc;
        qa[kk][0] = f2tf32(q0[0] * 0.125f);
        qa[kk][1] = f2tf32(q1[0] * 0.125f);
        qa[kk][2] = f2tf32(q0[4] * 0.125f);
        qa[kk][3] = f2tf32(q1[4] * 0.125f);
    }

    // ---- O accumulator (8 dk-tiles x 4), row stats in registers ----
    float o[8][4];
#pragma unroll
    for (int nt = 0; nt < 8; nt++) { o[nt][0] = o[nt][1] = o[nt][2] = o[nt][3] = 0.0f; }
    float m0 = -1e30f, m1 = -1e30f, l0 = 0.0f, l1 = 0.0f;

    // staging indices: 64x64 tile, 256 threads -> 16 floats each
    const int ld_row = tid >> 2;          // key 0..63
    const int ld_c   = (tid & 3) * 4;     // dk base, +16 per step

    const int prow0 = warp * 16 + gr;     // P rows for this thread
    const int prow1 = prow0 + 8;

    for (int jt = 0; jt < SS / 64; jt++) {
        // ---- stage K (row-major) and V (transposed), tf32 at store ----
        const float* Kt = Kb + (size_t)(jt * 64) * DK;
        const float* Vt = Vb + (size_t)(jt * 64) * DK;
#pragma unroll
        for (int p = 0; p < 4; p++) {
            int c = ld_c + p * 16;
            float4 kv = *(const float4*)&Kt[(size_t)ld_row * DK + c];
            float4 vv = *(const float4*)&Vt[(size_t)ld_row * DK + c];
            float* kd = &Ks[ld_row * LDK + c];
            kd[0] = __uint_as_float(f2tf32(kv.x));
            kd[1] = __uint_as_float(f2tf32(kv.y));
            kd[2] = __uint_as_float(f2tf32(kv.z));
            kd[3] = __uint_as_float(f2tf32(kv.w));
            VsT[(c + 0) * LDK + ld_row] = __uint_as_float(f2tf32(vv.x));
            VsT[(c + 1) * LDK + ld_row] = __uint_as_float(f2tf32(vv.y));
            VsT[(c + 2) * LDK + ld_row] = __uint_as_float(f2tf32(vv.z));
            VsT[(c + 3) * LDK + ld_row] = __uint_as_float(f2tf32(vv.w));
        }
        __syncthreads();

        // ---- S = (Q/8) @ K^T : 8 key-tiles x 8 k-steps ----
        float s[8][4];
#pragma unroll
        for (int nt = 0; nt < 8; nt++) { s[nt][0] = s[nt][1] = s[nt][2] = s[nt][3] = 0.0f; }
#pragma unroll
        for (int kk = 0; kk < 8; kk++) {
#pragma unroll
            for (int nt = 0; nt < 8; nt++) {
                // B[k][n] = K[key nt*8+gr][dk kk*8+gc(+4)]  (bank-perm 0..31)
                const float* kb = &Ks[(nt * 8 + gr) * LDK + kk * 8 + gc];
                uint32_t b0 = __float_as_uint(kb[0]);
                uint32_t b1 = __float_as_uint(kb[4]);
                mma_tf32(s[nt], qa[kk], b0, b1);
            }
        }

        // ---- online softmax in registers ----
        // rows: c0,c1 -> gr ; c2,c3 -> gr+8. cols span quad lanes (xor 1,2).
        float mx0 = -1e30f, mx1 = -1e30f;
#pragma unroll
        for (int nt = 0; nt < 8; nt++) {
            mx0 = fmaxf(mx0, fmaxf(s[nt][0], s[nt][1]));
            mx1 = fmaxf(mx1, fmaxf(s[nt][2], s[nt][3]));
        }
        mx0 = fmaxf(mx0, __shfl_xor_sync(0xffffffffu, mx0, 1));
        mx0 = fmaxf(mx0, __shfl_xor_sync(0xffffffffu, mx0, 2));
        mx1 = fmaxf(mx1, __shfl_xor_sync(0xffffffffu, mx1, 1));
        mx1 = fmaxf(mx1, __shfl_xor_sync(0xffffffffu, mx1, 2));

        float mn0 = fmaxf(m0, mx0), mn1 = fmaxf(m1, mx1);
        float sc0 = __expf(m0 - mn0), sc1 = __expf(m1 - mn1);
        float sum0 = 0.0f, sum1 = 0.0f;
#pragma unroll
        for (int nt = 0; nt < 8; nt++) {
            s[nt][0] = __expf(s[nt][0] - mn0);
            s[nt][1] = __expf(s[nt][1] - mn0);
            s[nt][2] = __expf(s[nt][2] - mn1);
            s[nt][3] = __expf(s[nt][3] - mn1);
            sum0 += s[nt][0] + s[nt][1];
            sum1 += s[nt][2] + s[nt][3];
        }
        sum0 += __shfl_xor_sync(0xffffffffu, sum0, 1);
        sum0 += __shfl_xor_sync(0xffffffffu, sum0, 2);
        sum1 += __shfl_xor_sync(0xffffffffu, sum1, 1);
        sum1 += __shfl_xor_sync(0xffffffffu, sum1, 2);
        l0 = l0 * sc0 + sum0;
        l1 = l1 * sc1 + sum1;
        m0 = mn0; m1 = mn1;

        // rescale O in registers (row-aligned with C-frag layout)
#pragma unroll
        for (int nt = 0; nt < 8; nt++) {
            o[nt][0] *= sc0; o[nt][1] *= sc0;
            o[nt][2] *= sc1; o[nt][3] *= sc1;
        }

        // ---- P -> per-warp SMEM (tf32 bits), C-layout -> A-layout ----
#pragma unroll
        for (int nt = 0; nt < 8; nt++) {
            float2 p0 = make_float2(__uint_as_float(f2tf32(s[nt][0])),
                                    __uint_as_float(f2tf32(s[nt][1])));
            float2 p1 = make_float2(__uint_as_float(f2tf32(s[nt][2])),
                                    __uint_as_float(f2tf32(s[nt][3])));
            *(float2*)&Ps[prow0 * LDK + nt * 8 + gc * 2] = p0;
            *(float2*)&Ps[prow1 * LDK + nt * 8 + gc * 2] = p1;
        }
        __syncwarp();

        // ---- O += P @ V : 8 key-steps x 8 dk-tiles ----
#pragma unroll
        for (int kk = 0; kk < 8; kk++) {
            uint32_t pa[4];
            const float* pp0 = &Ps[prow0 * LDK + kk * 8 + gc];
            const float* pp1 = &Ps[prow1 * LDK + kk * 8 + gc];
            pa[0] = __float_as_uint(pp0[0]);
            pa[1] = __float_as_uint(pp1[0]);
            pa[2] = __float_as_uint(pp0[4]);
            pa[3] = __float_as_uint(pp1[4]);
#pragma unroll
            for (int nt = 0; nt < 8; nt++) {
                // B[k][n] = V[key kk*8+gc(+4)][dk nt*8+gr] = VsT[dk][key]
                const float* vb = &VsT[(nt * 8 + gr) * LDK + kk * 8 + gc];
                uint32_t b0 = __float_as_uint(vb[0]);
                uint32_t b1 = __float_as_uint(vb[4]);
                mma_tf32(o[nt], pa, b0, b1);
            }
        }
        __syncthreads();   // all warps done reading K/V before restage
    }

    // ---- normalize + write merged-head layout (B,S,D) ----
    {
        int b = bh >> 4, h = bh & 15;
        float inv0 = 1.0f / l0, inv1 = 1.0f / l1;
        float* out0 = g_attn + ((size_t)(b * SS + qrow + gr))     * DM + h * DK;
        float* out1 = g_attn + ((size_t)(b * SS + qrow + gr + 8)) * DM + h * DK;
#pragma unroll
        for (int nt = 0; nt < 8; nt++) {
            *(float2*)&out0[nt * 8 + gc * 2] = make_float2(o[nt][0] * inv0, o[nt][1] * inv0);
            *(float2*)&out1[nt * 8 + gc * 2] = make_float2(o[nt][2] * inv1, o[nt][3] * inv1);
        }
    }
}

// ---------------------------------------------------------------------------
// Launcher. Inputs (metadata order): x, Wq, bq, Wk, bk, Wv, bv, Wo, bo
// ---------------------------------------------------------------------------
extern "C" void kernel_launch(void* const* d_in, const int* in_sizes, int n_in,
                              void* d_out, int out_size)
{
    const float* x  = (const float*)d_in[0];
    const float* Wq = (const float*)d_in[1];
    const float* bq = (const float*)d_in[2];
    const float* Wk = (const float*)d_in[3];
    const float* bk = (const float*)d_in[4];
    const float* Wv = (const float*)d_in[5];
    const float* bv = (const float*)d_in[6];
    const float* Wo = (const float*)d_in[7];
    const float* bo = (const float*)d_in[8];
    float* out = (float*)d_out;

    cudaFuncSetAttribute(flash_attn_kernel,
                         cudaFuncAttributeMaxDynamicSharedMemorySize, FLASH_SMEM_BYTES);

    // 1) QKV projections
    {
        dim3 grid(DM / 128, MTOT / 128, 3);
        gemm_tf32_kernel<1><<<grid, 256>>>(x, Wq, bq, Wk, bk, Wv, bv, nullptr);
    }
    // 2) flash attention (128-row q tiles)
    {
        dim3 grid(SS / 128, BB * HEADS);
        flash_attn_kernel<<<grid, 256, FLASH_SMEM_BYTES>>>();
    }
    // 3) output projection
    {
        dim3 grid(DM / 128, MTOT / 128, 1);
        gemm_tf32_kernel<0><<<grid, 256>>>(nullptr, Wo, bo, nullptr, nullptr, nullptr, nullptr, out);
    }
}

// round 5
// speedup vs baseline: 2.0835x; 1.0158x over previous
#include <cuda_runtime.h>
#include <mma.h>
#include <cstdint>

using namespace nvcuda;

// Problem constants
#define DM    1024          // d_model
#define HEADS 16
#define DK    64            // head dim
#define BB    4             // batch
#define SS    2048          // seq len
#define MTOT  (BB * SS)     // 8192 rows

// ---------------------------------------------------------------------------
// Scratch (device globals — no cudaMalloc allowed).
// Only referenced from device code (host-shadow aliasing was the R1 bug).
// ---------------------------------------------------------------------------
__device__ float g_Q[(size_t)MTOT * DM];     // (B,H,S,DK) layout
__device__ float g_K[(size_t)MTOT * DM];     // (B,H,S,DK) layout
__device__ float g_V[(size_t)MTOT * DM];     // (B,H,S,DK) layout
__device__ float g_attn[(size_t)MTOT * DM];  // (B,S,D) merged-head layout

// ---------------------------------------------------------------------------
// Helpers
// ---------------------------------------------------------------------------
__device__ __forceinline__ uint32_t f2tf32(float x) {
    uint32_t u;
    asm("cvt.rna.tf32.f32 %0, %1;" : "=r"(u) : "f"(x));
    return u;
}

template <typename Frag>
__device__ __forceinline__ void frag_to_tf32(Frag& f) {
#pragma unroll
    for (int i = 0; i < f.num_elements; i++)
        f.x[i] = wmma::__float_to_tf32(f.x[i]);
}

__device__ __forceinline__ void cp_async16(void* smem_ptr, const void* gptr) {
    uint32_t sa = (uint32_t)__cvta_generic_to_shared(smem_ptr);
    asm volatile("cp.async.cg.shared.global [%0], [%1], 16;\n" :: "r"(sa), "l"(gptr));
}
__device__ __forceinline__ void cp_commit() {
    asm volatile("cp.async.commit_group;\n");
}
template <int N>
__device__ __forceinline__ void cp_wait() {
    asm volatile("cp.async.wait_group %0;\n" :: "n"(N));
}

// mma.m16n8k8 tf32: C(16x8,f32) += A(16x8,row) * B(8x8,col)
__device__ __forceinline__ void mma_tf32(float c[4], const uint32_t a[4],
                                         uint32_t b0, uint32_t b1) {
    asm volatile(
        "mma.sync.aligned.m16n8k8.row.col.f32.tf32.tf32.f32 "
        "{%0,%1,%2,%3}, {%4,%5,%6,%7}, {%8,%9}, {%0,%1,%2,%3};"
        : "+f"(c[0]), "+f"(c[1]), "+f"(c[2]), "+f"(c[3])
        : "r"(a[0]), "r"(a[1]), "r"(a[2]), "r"(a[3]), "r"(b0), "r"(b1));
}

// ---------------------------------------------------------------------------
// GEMM v2: C = A @ W + bias. cp.async double-buffered, K-tile 32.
// Block tile 128x128, 8 warps (warp tile 32x64: 2x4 frags of 16x16).
// SMEM (dynamic, floats): As[2][128][36] | Bs[2][32][132]. Raw fp32 staged;
// tf32 RNA conversion at fragment-load time. Epilogue aliases As region.
// MODE 0: A = g_attn -> Cplain. MODE 1: A = x; z selects Wq/Wk/Wv; head-split.
// ---------------------------------------------------------------------------
#define KT     32
#define LDA    36
#define LDB    132
#define A_BUF  (128 * LDA)
#define B_BUF  (KT * LDB)
#define GEMM_SMEM_BYTES ((2 * A_BUF + 2 * B_BUF) * (int)sizeof(float))

template <int MODE>
__global__ __launch_bounds__(256, 2)
void gemm_tf32_kernel(const float* __restrict__ Ain,
                      const float* __restrict__ W0, const float* __restrict__ b0,
                      const float* __restrict__ W1, const float* __restrict__ b1,
                      const float* __restrict__ W2, const float* __restrict__ b2,
                      float* __restrict__ Cplain)
{
    extern __shared__ float sm[];
    float* As = sm;               // [2][128][LDA]
    float* Bs = sm + 2 * A_BUF;   // [2][KT][LDB]

    const int z = blockIdx.z;
    const float* A    = (MODE == 0) ? (const float*)g_attn : Ain;
    const float* W    = (MODE == 0) ? W0 : (z == 0 ? W0 : (z == 1 ? W1 : W2));
    const float* bias = (MODE == 0) ? b0 : (z == 0 ? b0 : (z == 1 ? b1 : b2));
    float* C = (MODE == 0) ? Cplain : (z == 0 ? g_Q : (z == 1 ? g_K : g_V));

    const int tid  = threadIdx.x;
    const int warp = tid >> 5;
    const int lane = tid & 31;
    const int wm   = warp >> 1;
    const int wn   = warp & 1;
    const int m0   = blockIdx.y * 128;
    const int n0   = blockIdx.x * 128;

    // A tile 128x32 = 1024 float4; 4 per thread. row = id/8, col4 = (id%8)*4
    const int a_row = tid >> 3;          // +32 per step (4 steps)
    const int a_c4  = (tid & 7) * 4;
    // B tile 32x128 = 1024 float4; row = id/32, col4 = (id%32)*4
    const int b_row = tid >> 5;          // +8 per step
    const int b_c4  = (tid & 31) * 4;

    auto stage = [&](int buf, int k0) {
        float* ad = As + buf * A_BUF;
        float* bd = Bs + buf * B_BUF;
#pragma unroll
        for (int t = 0; t < 4; t++) {
            int r = a_row + t * 32;
            cp_async16(&ad[r * LDA + a_c4], &A[(size_t)(m0 + r) * DM + k0 + a_c4]);
        }
#pragma unroll
        for (int t = 0; t < 4; t++) {
            int r = b_row + t * 8;
            cp_async16(&bd[r * LDB + b_c4], &W[(size_t)(k0 + r) * DM + n0 + b_c4]);
        }
        cp_commit();
    };

    wmma::fragment<wmma::accumulator, 16, 16, 8, float> acc[2][4];
#pragma unroll
    for (int im = 0; im < 2; im++)
#pragma unroll
        for (int in = 0; in < 4; in++)
            wmma::fill_fragment(acc[im][in], 0.0f);

    stage(0, 0);

    const int NT = DM / KT;   // 32
    for (int t = 0; t < NT; t++) {
        int buf = t & 1;
        if (t + 1 < NT) {
            stage(buf ^ 1, (t + 1) * KT);
            cp_wait<1>();
        } else {
            cp_wait<0>();
        }
        __syncthreads();

        const float* av = As + buf * A_BUF;
        const float* bv = Bs + buf * B_BUF;
#pragma unroll
        for (int ks = 0; ks < 4; ks++) {
            wmma::fragment<wmma::matrix_a, 16, 16, 8, wmma::precision::tf32, wmma::row_major> af[2];
            wmma::fragment<wmma::matrix_b, 16, 16, 8, wmma::precision::tf32, wmma::row_major> bf[4];
#pragma unroll
            for (int im = 0; im < 2; im++) {
                wmma::load_matrix_sync(af[im], &av[(wm * 32 + im * 16) * LDA + ks * 8], LDA);
                frag_to_tf32(af[im]);
            }
#pragma unroll
            for (int in = 0; in < 4; in++) {
                wmma::load_matrix_sync(bf[in], &bv[(ks * 8) * LDB + wn * 64 + in * 16], LDB);
                frag_to_tf32(bf[in]);
            }
#pragma unroll
            for (int im = 0; im < 2; im++)
#pragma unroll
                for (int in = 0; in < 4; in++)
                    wmma::mma_sync(acc[im][in], af[im], bf[in], acc[im][in]);
        }
        __syncthreads();
    }

    // --- epilogue: frag -> smem (aliases As) -> global (+bias, layout map) ---
    float* epi = sm + warp * 256;
#pragma unroll
    for (int im = 0; im < 2; im++) {
#pragma unroll
        for (int in = 0; in < 4; in++) {
            wmma::store_matrix_sync(epi, acc[im][in], 16, wmma::mem_row_major);
            __syncwarp();
#pragma unroll
            for (int i = 0; i < 8; i++) {
                int v = lane * 8 + i;
                int r = v >> 4, c = v & 15;
                int gm = m0 + wm * 32 + im * 16 + r;
                int gn = n0 + wn * 64 + in * 16 + c;
                float val = epi[v] + bias[gn];
                if (MODE == 0) {
                    C[(size_t)gm * DM + gn] = val;
                } else {
                    int b = gm >> 11, s = gm & 2047;
                    int h = gn >> 6,  d = gn & 63;
                    C[(((size_t)(b * HEADS + h)) * SS + s) * DK + d] = val;
                }
            }
            __syncwarp();
        }
    }
}

// ---------------------------------------------------------------------------
// Flash attention (unchanged from R4 — known good, ~580us)
// ---------------------------------------------------------------------------
#define LDKf 68
#define FLASH_SMEM_BYTES ((2 * 64 * LDKf + 128 * LDKf) * (int)sizeof(float))

__global__ __launch_bounds__(256, 2)
void flash_attn_kernel()
{
    extern __shared__ float smf[];
    float* Ks  = smf;                  // [64 keys][LDKf]
    float* VsT = smf + 64 * LDKf;      // [64 dk][LDKf] (transposed)
    float* Ps  = smf + 2 * 64 * LDKf;  // [128 rows][LDKf]

    const int tid  = threadIdx.x;
    const int warp = tid >> 5;
    const int lane = tid & 31;
    const int gr   = lane >> 2;
    const int gc   = lane & 3;
    const int qt   = blockIdx.x;
    const int bh   = blockIdx.y;

    const float* Qb = g_Q + (size_t)bh * SS * DK;
    const float* Kb = g_K + (size_t)bh * SS * DK;
    const float* Vb = g_V + (size_t)bh * SS * DK;

    const int qrow = qt * 128 + warp * 16;

    uint32_t qa[8][4];
#pragma unroll
    for (int kk = 0; kk < 8; kk++) {
        const float* q0 = Qb + (size_t)(qrow + gr)     * DK + kk * 8 + gc;
        const float* q1 = Qb + (size_t)(qrow + gr + 8) * DK + kk * 8 + gc;
        qa[kk][0] = f2tf32(q0[0] * 0.125f);
        qa[kk][1] = f2tf32(q1[0] * 0.125f);
        qa[kk][2] = f2tf32(q0[4] * 0.125f);
        qa[kk][3] = f2tf32(q1[4] * 0.125f);
    }

    float o[8][4];
#pragma unroll
    for (int nt = 0; nt < 8; nt++) { o[nt][0] = o[nt][1] = o[nt][2] = o[nt][3] = 0.0f; }
    float m0 = -1e30f, m1 = -1e30f, l0 = 0.0f, l1 = 0.0f;

    const int ld_row = tid >> 2;
    const int ld_c   = (tid & 3) * 4;

    const int prow0 = warp * 16 + gr;
    const int prow1 = prow0 + 8;

    for (int jt = 0; jt < SS / 64; jt++) {
        const float* Kt = Kb + (size_t)(jt * 64) * DK;
        const float* Vt = Vb + (size_t)(jt * 64) * DK;
#pragma unroll
        for (int p = 0; p < 4; p++) {
            int c = ld_c + p * 16;
            float4 kv = *(const float4*)&Kt[(size_t)ld_row * DK + c];
            float4 vv = *(const float4*)&Vt[(size_t)ld_row * DK + c];
            float* kd = &Ks[ld_row * LDKf + c];
            kd[0] = __uint_as_float(f2tf32(kv.x));
            kd[1] = __uint_as_float(f2tf32(kv.y));
            kd[2] = __uint_as_float(f2tf32(kv.z));
            kd[3] = __uint_as_float(f2tf32(kv.w));
            VsT[(c + 0) * LDKf + ld_row] = __uint_as_float(f2tf32(vv.x));
            VsT[(c + 1) * LDKf + ld_row] = __uint_as_float(f2tf32(vv.y));
            VsT[(c + 2) * LDKf + ld_row] = __uint_as_float(f2tf32(vv.z));
            VsT[(c + 3) * LDKf + ld_row] = __uint_as_float(f2tf32(vv.w));
        }
        __syncthreads();

        float s[8][4];
#pragma unroll
        for (int nt = 0; nt < 8; nt++) { s[nt][0] = s[nt][1] = s[nt][2] = s[nt][3] = 0.0f; }
#pragma unroll
        for (int kk = 0; kk < 8; kk++) {
#pragma unroll
            for (int nt = 0; nt < 8; nt++) {
                const float* kb = &Ks[(nt * 8 + gr) * LDKf + kk * 8 + gc];
                uint32_t b0 = __float_as_uint(kb[0]);
                uint32_t b1 = __float_as_uint(kb[4]);
                mma_tf32(s[nt], qa[kk], b0, b1);
            }
        }

        float mx0 = -1e30f, mx1 = -1e30f;
#pragma unroll
        for (int nt = 0; nt < 8; nt++) {
            mx0 = fmaxf(mx0, fmaxf(s[nt][0], s[nt][1]));
            mx1 = fmaxf(mx1, fmaxf(s[nt][2], s[nt][3]));
        }
        mx0 = fmaxf(mx0, __shfl_xor_sync(0xffffffffu, mx0, 1));
        mx0 = fmaxf(mx0, __shfl_xor_sync(0xffffffffu, mx0, 2));
        mx1 = fmaxf(mx1, __shfl_xor_sync(0xffffffffu, mx1, 1));
        mx1 = fmaxf(mx1, __shfl_xor_sync(0xffffffffu, mx1, 2));

        float mn0 = fmaxf(m0, mx0), mn1 = fmaxf(m1, mx1);
        float sc0 = __expf(m0 - mn0), sc1 = __expf(m1 - mn1);
        float sum0 = 0.0f, sum1 = 0.0f;
#pragma unroll
        for (int nt = 0; nt < 8; nt++) {
            s[nt][0] = __expf(s[nt][0] - mn0);
            s[nt][1] = __expf(s[nt][1] - mn0);
            s[nt][2] = __expf(s[nt][2] - mn1);
            s[nt][3] = __expf(s[nt][3] - mn1);
            sum0 += s[nt][0] + s[nt][1];
            sum1 += s[nt][2] + s[nt][3];
        }
        sum0 += __shfl_xor_sync(0xffffffffu, sum0, 1);
        sum0 += __shfl_xor_sync(0xffffffffu, sum0, 2);
        sum1 += __shfl_xor_sync(0xffffffffu, sum1, 1);
        sum1 += __shfl_xor_sync(0xffffffffu, sum1, 2);
        l0 = l0 * sc0 + sum0;
        l1 = l1 * sc1 + sum1;
        m0 = mn0; m1 = mn1;

#pragma unroll
        for (int nt = 0; nt < 8; nt++) {
            o[nt][0] *= sc0; o[nt][1] *= sc0;
            o[nt][2] *= sc1; o[nt][3] *= sc1;
        }

#pragma unroll
        for (int nt = 0; nt < 8; nt++) {
            float2 p0 = make_float2(__uint_as_float(f2tf32(s[nt][0])),
                                    __uint_as_float(f2tf32(s[nt][1])));
            float2 p1 = make_float2(__uint_as_float(f2tf32(s[nt][2])),
                                    __uint_as_float(f2tf32(s[nt][3])));
            *(float2*)&Ps[prow0 * LDKf + nt * 8 + gc * 2] = p0;
            *(float2*)&Ps[prow1 * LDKf + nt * 8 + gc * 2] = p1;
        }
        __syncwarp();

#pragma unroll
        for (int kk = 0; kk < 8; kk++) {
            uint32_t pa[4];
            const float* pp0 = &Ps[prow0 * LDKf + kk * 8 + gc];
            const float* pp1 = &Ps[prow1 * LDKf + kk * 8 + gc];
            pa[0] = __float_as_uint(pp0[0]);
            pa[1] = __float_as_uint(pp1[0]);
            pa[2] = __float_as_uint(pp0[4]);
            pa[3] = __float_as_uint(pp1[4]);
#pragma unroll
            for (int nt = 0; nt < 8; nt++) {
                const float* vb = &VsT[(nt * 8 + gr) * LDKf + kk * 8 + gc];
                uint32_t b0 = __float_as_uint(vb[0]);
                uint32_t b1 = __float_as_uint(vb[4]);
                mma_tf32(o[nt], pa, b0, b1);
            }
        }
        __syncthreads();
    }

    {
        int b = bh >> 4, h = bh & 15;
        float inv0 = 1.0f / l0, inv1 = 1.0f / l1;
        float* out0 = g_attn + ((size_t)(b * SS + qrow + gr))     * DM + h * DK;
        float* out1 = g_attn + ((size_t)(b * SS + qrow + gr + 8)) * DM + h * DK;
#pragma unroll
        for (int nt = 0; nt < 8; nt++) {
            *(float2*)&out0[nt * 8 + gc * 2] = make_float2(o[nt][0] * inv0, o[nt][1] * inv0);
            *(float2*)&out1[nt * 8 + gc * 2] = make_float2(o[nt][2] * inv1, o[nt][3] * inv1);
        }
    }
}

// ---------------------------------------------------------------------------
// Launcher. Inputs (metadata order): x, Wq, bq, Wk, bk, Wv, bv, Wo, bo
// ---------------------------------------------------------------------------
extern "C" void kernel_launch(void* const* d_in, const int* in_sizes, int n_in,
                              void* d_out, int out_size)
{
    const float* x  = (const float*)d_in[0];
    const float* Wq = (const float*)d_in[1];
    const float* bq = (const float*)d_in[2];
    const float* Wk = (const float*)d_in[3];
    const float* bk = (const float*)d_in[4];
    const float* Wv = (const float*)d_in[5];
    const float* bv = (const float*)d_in[6];
    const float* Wo = (const float*)d_in[7];
    const float* bo = (const float*)d_in[8];
    float* out = (float*)d_out;

    cudaFuncSetAttribute(gemm_tf32_kernel<1>,
                         cudaFuncAttributeMaxDynamicSharedMemorySize, GEMM_SMEM_BYTES);
    cudaFuncSetAttribute(gemm_tf32_kernel<0>,
                         cudaFuncAttributeMaxDynamicSharedMemorySize, GEMM_SMEM_BYTES);
    cudaFuncSetAttribute(flash_attn_kernel,
                         cudaFuncAttributeMaxDynamicSharedMemorySize, FLASH_SMEM_BYTES);

    // 1) QKV projections
    {
        dim3 grid(DM / 128, MTOT / 128, 3);
        gemm_tf32_kernel<1><<<grid, 256, GEMM_SMEM_BYTES>>>(x, Wq, bq, Wk, bk, Wv, bv, nullptr);
    }
    // 2) flash attention (128-row q tiles)
    {
        dim3 grid(SS / 128, BB * HEADS);
        flash_attn_kernel<<<grid, 256, FLASH_SMEM_BYTES>>>();
    }
    // 3) output projection
    {
        dim3 grid(DM / 128, MTOT / 128, 1);
        gemm_tf32_kernel<0><<<grid, 256, GEMM_SMEM_BYTES>>>(nullptr, Wo, bo, nullptr, nullptr, nullptr, nullptr, out);
    }
}

// round 6
// speedup vs baseline: 4.5153x; 2.1672x over previous
#include <cuda_runtime.h>
#include <cuda_fp16.h>
#include <mma.h>
#include <cstdint>

using namespace nvcuda;

// Problem constants
#define DM    1024          // d_model
#define HEADS 16
#define DK    64            // head dim
#define BB    4             // batch
#define SS    2048          // seq len
#define MTOT  (BB * SS)     // 8192 rows

// ---------------------------------------------------------------------------
// Scratch (device globals — no cudaMalloc allowed).
// Only referenced from device code (host-shadow aliasing was the R1 bug).
// ---------------------------------------------------------------------------
__device__ __half g_xh[(size_t)MTOT * DM];      // x in fp16
__device__ __half g_Wh[4][(size_t)DM * DM];     // Wq, Wk, Wv, Wo in fp16
__device__ __half g_Qh[(size_t)MTOT * DM];      // (B,H,S,DK)
__device__ __half g_Kh[(size_t)MTOT * DM];      // (B,H,S,DK)
__device__ __half g_Vh[(size_t)MTOT * DM];      // (B,H,S,DK)
__device__ __half g_attnh[(size_t)MTOT * DM];   // (B,S,D)

// ---------------------------------------------------------------------------
// Helpers
// ---------------------------------------------------------------------------
__device__ __forceinline__ uint32_t h2u(__half2 h) {
    return *reinterpret_cast<uint32_t*>(&h);
}

__device__ __forceinline__ void cp_async16(void* smem_ptr, const void* gptr) {
    uint32_t sa = (uint32_t)__cvta_generic_to_shared(smem_ptr);
    asm volatile("cp.async.cg.shared.global [%0], [%1], 16;\n" :: "r"(sa), "l"(gptr));
}
__device__ __forceinline__ void cp_commit() {
    asm volatile("cp.async.commit_group;\n");
}
template <int N>
__device__ __forceinline__ void cp_wait() {
    asm volatile("cp.async.wait_group %0;\n" :: "n"(N));
}

// mma.m16n8k16 fp16: C(16x8,f32) += A(16x16,row) * B(16x8,col)
__device__ __forceinline__ void mma_f16(float c[4], const uint32_t a[4],
                                        uint32_t b0, uint32_t b1) {
    asm volatile(
        "mma.sync.aligned.m16n8k16.row.col.f32.f16.f16.f32 "
        "{%0,%1,%2,%3}, {%4,%5,%6,%7}, {%8,%9}, {%0,%1,%2,%3};"
        : "+f"(c[0]), "+f"(c[1]), "+f"(c[2]), "+f"(c[3])
        : "r"(a[0]), "r"(a[1]), "r"(a[2]), "r"(a[3]), "r"(b0), "r"(b1));
}

// ---------------------------------------------------------------------------
// fp32 -> fp16 conversion. dst_sel: 0 = g_xh, 1..4 = g_Wh[0..3].
// Each thread converts 8 floats -> one 16B half store.
// ---------------------------------------------------------------------------
__global__ void f2h_kernel(const float* __restrict__ src, int dst_sel, int n8)
{
    int i = blockIdx.x * blockDim.x + threadIdx.x;
    if (i >= n8) return;
    __half* dst = (dst_sel == 0) ? g_xh : g_Wh[dst_sel - 1];
    const float4* s4 = (const float4*)src;
    float4 v0 = s4[i * 2];
    float4 v1 = s4[i * 2 + 1];
    __half2 h[4];
    h[0] = __floats2half2_rn(v0.x, v0.y);
    h[1] = __floats2half2_rn(v0.z, v0.w);
    h[2] = __floats2half2_rn(v1.x, v1.y);
    h[3] = __floats2half2_rn(v1.z, v1.w);
    *(uint4*)&dst[(size_t)i * 8] = *(uint4*)h;
}

// ---------------------------------------------------------------------------
// GEMM v3 (fp16 in, fp32 acc): C = A @ W + bias. cp.async double-buffered,
// K-tile 32, block tile 128x128, 8 warps (warp 32x64, wmma 16x16x16).
// MODE 1: A = g_xh, W = g_Wh[z], C = g_Qh/g_Kh/g_Vh half head-split.
// MODE 0: A = g_attnh, W = g_Wh[3], C = float out (+bias).
// ---------------------------------------------------------------------------
#define KT      32
#define LDA_H   40
#define LDB_H   136
#define A_BUFH  (128 * LDA_H)
#define B_BUFH  (KT * LDB_H)
#define GEMM_SMEM_BYTES ((2 * A_BUFH + 2 * B_BUFH) * (int)sizeof(__half))

template <int MODE>
__global__ __launch_bounds__(256, 2)
void gemm_f16_kernel(const float* __restrict__ b0p,
                     const float* __restrict__ b1p,
                     const float* __restrict__ b2p,
                     float* __restrict__ Cout)
{
    extern __shared__ __half smh[];
    __half* As = smh;                // [2][128][LDA_H]
    __half* Bs = smh + 2 * A_BUFH;   // [2][KT][LDB_H]

    const int z = blockIdx.z;
    const __half* A = (MODE == 0) ? (const __half*)g_attnh : (const __half*)g_xh;
    const __half* W = (MODE == 0) ? g_Wh[3] : g_Wh[z];
    const float* bias = (MODE == 0) ? b0p : (z == 0 ? b0p : (z == 1 ? b1p : b2p));
    __half* Ch = (MODE == 0) ? nullptr : (z == 0 ? g_Qh : (z == 1 ? g_Kh : g_Vh));

    const int tid  = threadIdx.x;
    const int warp = tid >> 5;
    const int lane = tid & 31;
    const int wm   = warp >> 1;
    const int wn   = warp & 1;
    const int m0   = blockIdx.y * 128;
    const int n0   = blockIdx.x * 128;

    auto stage = [&](int buf, int k0) {
        __half* ad = As + buf * A_BUFH;
        __half* bd = Bs + buf * B_BUFH;
#pragma unroll
        for (int t = 0; t < 2; t++) {            // A: 128 rows x 4 chunks
            int id = tid + t * 256;
            int r = id >> 2, c = (id & 3) * 8;
            cp_async16(&ad[r * LDA_H + c], &A[(size_t)(m0 + r) * DM + k0 + c]);
        }
#pragma unroll
        for (int t = 0; t < 2; t++) {            // B: 32 rows x 16 chunks
            int id = tid + t * 256;
            int r = id >> 4, c = (id & 15) * 8;
            cp_async16(&bd[r * LDB_H + c], &W[(size_t)(k0 + r) * DM + n0 + c]);
        }
        cp_commit();
    };

    wmma::fragment<wmma::accumulator, 16, 16, 16, float> acc[2][4];
#pragma unroll
    for (int im = 0; im < 2; im++)
#pragma unroll
        for (int in = 0; in < 4; in++)
            wmma::fill_fragment(acc[im][in], 0.0f);

    stage(0, 0);

    const int NT = DM / KT;   // 32
    for (int t = 0; t < NT; t++) {
        int buf = t & 1;
        if (t + 1 < NT) {
            stage(buf ^ 1, (t + 1) * KT);
            cp_wait<1>();
        } else {
            cp_wait<0>();
        }
        __syncthreads();

        const __half* av = As + buf * A_BUFH;
        const __half* bv = Bs + buf * B_BUFH;
#pragma unroll
        for (int ks = 0; ks < 2; ks++) {
            wmma::fragment<wmma::matrix_a, 16, 16, 16, __half, wmma::row_major> af[2];
            wmma::fragment<wmma::matrix_b, 16, 16, 16, __half, wmma::row_major> bf[4];
#pragma unroll
            for (int im = 0; im < 2; im++)
                wmma::load_matrix_sync(af[im], &av[(wm * 32 + im * 16) * LDA_H + ks * 16], LDA_H);
#pragma unroll
            for (int in = 0; in < 4; in++)
                wmma::load_matrix_sync(bf[in], &bv[(ks * 16) * LDB_H + wn * 64 + in * 16], LDB_H);
#pragma unroll
            for (int im = 0; im < 2; im++)
#pragma unroll
                for (int in = 0; in < 4; in++)
                    wmma::mma_sync(acc[im][in], af[im], bf[in], acc[im][in]);
        }
        __syncthreads();
    }

    // --- epilogue: frag -> smem (aliases As) -> global (+bias, layout map) ---
    float* epi = (float*)smh + warp * 256;
#pragma unroll
    for (int im = 0; im < 2; im++) {
#pragma unroll
        for (int in = 0; in < 4; in++) {
            wmma::store_matrix_sync(epi, acc[im][in], 16, wmma::mem_row_major);
            __syncwarp();
#pragma unroll
            for (int i = 0; i < 8; i++) {
                int v = lane * 8 + i;
                int r = v >> 4, c = v & 15;
                int gm = m0 + wm * 32 + im * 16 + r;
                int gn = n0 + wn * 64 + in * 16 + c;
                float val = epi[v] + bias[gn];
                if (MODE == 0) {
                    Cout[(size_t)gm * DM + gn] = val;
                } else {
                    int b = gm >> 11, s = gm & 2047;
                    int h = gn >> 6,  d = gn & 63;
                    Ch[(((size_t)(b * HEADS + h)) * SS + s) * DK + d] = __float2half_rn(val);
                }
            }
            __syncwarp();
        }
    }
}

// ---------------------------------------------------------------------------
// Flash attention v4 — fp16 m16n8k16. 128 q rows/block, 8 warps; each warp
// 16 rows x dk=64. Q/S/O in registers; P converts C-frag -> A-frag entirely
// in registers (fp16 layout identity) — no P SMEM, no extra syncs.
// SMEM: Ks[64][72] half (row-major), VsT[64][72] half (transposed).
// ---------------------------------------------------------------------------
#define LDH 72
#define FLASH_SMEM_BYTES (2 * 64 * LDH * (int)sizeof(__half))

__global__ __launch_bounds__(256, 2)
void flash_attn_kernel()
{
    extern __shared__ __half smf[];
    __half* Ks  = smf;             // [64 keys][LDH]
    __half* VsT = smf + 64 * LDH;  // [64 dk][LDH] (key-contiguous rows)

    const int tid  = threadIdx.x;
    const int warp = tid >> 5;
    const int lane = tid & 31;
    const int gr   = lane >> 2;    // 0..7
    const int gc   = lane & 3;     // 0..3
    const int qt   = blockIdx.x;   // 0..15
    const int bh   = blockIdx.y;   // 0..63

    const __half* Qb = g_Qh + (size_t)bh * SS * DK;
    const __half* Kb = g_Kh + (size_t)bh * SS * DK;
    const __half* Vb = g_Vh + (size_t)bh * SS * DK;

    const int qrow = qt * 128 + warp * 16;

    // ---- Q as A-fragments (4 k16-steps x 4 regs), pre-scaled by 1/8 ----
    const __half2 sc2 = __float2half2_rn(0.125f);
    uint32_t qa[4][4];
#pragma unroll
    for (int kk = 0; kk < 4; kk++) {
        const __half* q0 = Qb + (size_t)(qrow + gr)     * DK + kk * 16 + 2 * gc;
        const __half* q1 = Qb + (size_t)(qrow + gr + 8) * DK + kk * 16 + 2 * gc;
        qa[kk][0] = h2u(__hmul2(*(const __half2*)(q0),     sc2));
        qa[kk][1] = h2u(__hmul2(*(const __half2*)(q1),     sc2));
        qa[kk][2] = h2u(__hmul2(*(const __half2*)(q0 + 8), sc2));
        qa[kk][3] = h2u(__hmul2(*(const __half2*)(q1 + 8), sc2));
    }

    float o[8][4];
#pragma unroll
    for (int nt = 0; nt < 8; nt++) { o[nt][0] = o[nt][1] = o[nt][2] = o[nt][3] = 0.0f; }
    float m0 = -1e30f, m1 = -1e30f, l0 = 0.0f, l1 = 0.0f;

    for (int jt = 0; jt < SS / 64; jt++) {
        // ---- stage K (row-major) and V (transposed) ----
        const __half* Kt = Kb + (size_t)(jt * 64) * DK;
        const __half* Vt = Vb + (size_t)(jt * 64) * DK;
#pragma unroll
        for (int rep = 0; rep < 2; rep++) {
            int id  = tid + rep * 256;       // 512 chunks of 8 halfs
            int key = id >> 3;
            int c8  = (id & 7) * 8;
            uint4 kraw = *(const uint4*)&Kt[(size_t)key * DK + c8];
            *(uint4*)&Ks[key * LDH + c8] = kraw;
            uint4 vraw = *(const uint4*)&Vt[(size_t)key * DK + c8];
            const __half* vh = (const __half*)&vraw;
#pragma unroll
            for (int j = 0; j < 8; j++)
                VsT[(c8 + j) * LDH + key] = vh[j];
        }
        __syncthreads();

        // ---- S = (Q/8) @ K^T : 4 k16-steps x 8 key-tiles ----
        float s[8][4];
#pragma unroll
        for (int nt = 0; nt < 8; nt++) { s[nt][0] = s[nt][1] = s[nt][2] = s[nt][3] = 0.0f; }
#pragma unroll
        for (int kk = 0; kk < 4; kk++) {
#pragma unroll
            for (int nt = 0; nt < 8; nt++) {
                const __half* kb = &Ks[(nt * 8 + gr) * LDH + kk * 16 + 2 * gc];
                uint32_t b0 = h2u(*(const __half2*)(kb));
                uint32_t b1 = h2u(*(const __half2*)(kb + 8));
                mma_f16(s[nt], qa[kk], b0, b1);
            }
        }

        // ---- online softmax in registers ----
        float mx0 = -1e30f, mx1 = -1e30f;
#pragma unroll
        for (int nt = 0; nt < 8; nt++) {
            mx0 = fmaxf(mx0, fmaxf(s[nt][0], s[nt][1]));
            mx1 = fmaxf(mx1, fmaxf(s[nt][2], s[nt][3]));
        }
        mx0 = fmaxf(mx0, __shfl_xor_sync(0xffffffffu, mx0, 1));
        mx0 = fmaxf(mx0, __shfl_xor_sync(0xffffffffu, mx0, 2));
        mx1 = fmaxf(mx1, __shfl_xor_sync(0xffffffffu, mx1, 1));
        mx1 = fmaxf(mx1, __shfl_xor_sync(0xffffffffu, mx1, 2));

        float mn0 = fmaxf(m0, mx0), mn1 = fmaxf(m1, mx1);
        float sc0 = __expf(m0 - mn0), sc1 = __expf(m1 - mn1);
        float sum0 = 0.0f, sum1 = 0.0f;
#pragma unroll
        for (int nt = 0; nt < 8; nt++) {
            s[nt][0] = __expf(s[nt][0] - mn0);
            s[nt][1] = __expf(s[nt][1] - mn0);
            s[nt][2] = __expf(s[nt][2] - mn1);
            s[nt][3] = __expf(s[nt][3] - mn1);
            sum0 += s[nt][0] + s[nt][1];
            sum1 += s[nt][2] + s[nt][3];
        }
        sum0 += __shfl_xor_sync(0xffffffffu, sum0, 1);
        sum0 += __shfl_xor_sync(0xffffffffu, sum0, 2);
        sum1 += __shfl_xor_sync(0xffffffffu, sum1, 1);
        sum1 += __shfl_xor_sync(0xffffffffu, sum1, 2);
        l0 = l0 * sc0 + sum0;
        l1 = l1 * sc1 + sum1;
        m0 = mn0; m1 = mn1;

#pragma unroll
        for (int nt = 0; nt < 8; nt++) {
            o[nt][0] *= sc0; o[nt][1] *= sc0;
            o[nt][2] *= sc1; o[nt][3] *= sc1;
        }

        // ---- O += P @ V : P C-frag -> A-frag in registers (fp16 identity) ----
#pragma unroll
        for (int t = 0; t < 4; t++) {
            uint32_t pa[4];
            pa[0] = h2u(__floats2half2_rn(s[2 * t][0],     s[2 * t][1]));
            pa[1] = h2u(__floats2half2_rn(s[2 * t][2],     s[2 * t][3]));
            pa[2] = h2u(__floats2half2_rn(s[2 * t + 1][0], s[2 * t + 1][1]));
            pa[3] = h2u(__floats2half2_rn(s[2 * t + 1][2], s[2 * t + 1][3]));
#pragma unroll
            for (int nt = 0; nt < 8; nt++) {
                const __half* vb = &VsT[(nt * 8 + gr) * LDH + t * 16 + 2 * gc];
                uint32_t b0 = h2u(*(const __half2*)(vb));
                uint32_t b1 = h2u(*(const __half2*)(vb + 8));
                mma_f16(o[nt], pa, b0, b1);
            }
        }
        __syncthreads();
    }

    // ---- normalize + write merged-head half layout (B,S,D) ----
    {
        int b = bh >> 4, h = bh & 15;
        float inv0 = 1.0f / l0, inv1 = 1.0f / l1;
        __half* out0 = g_attnh + ((size_t)(b * SS + qrow + gr))     * DM + h * DK;
        __half* out1 = g_attnh + ((size_t)(b * SS + qrow + gr + 8)) * DM + h * DK;
#pragma unroll
        for (int nt = 0; nt < 8; nt++) {
            *(__half2*)&out0[nt * 8 + gc * 2] = __floats2half2_rn(o[nt][0] * inv0, o[nt][1] * inv0);
            *(__half2*)&out1[nt * 8 + gc * 2] = __floats2half2_rn(o[nt][2] * inv1, o[nt][3] * inv1);
        }
    }
}

// ---------------------------------------------------------------------------
// Launcher. Inputs (metadata order): x, Wq, bq, Wk, bk, Wv, bv, Wo, bo
// ---------------------------------------------------------------------------
extern "C" void kernel_launch(void* const* d_in, const int* in_sizes, int n_in,
                              void* d_out, int out_size)
{
    const float* x  = (const float*)d_in[0];
    const float* Wq = (const float*)d_in[1];
    const float* bq = (const float*)d_in[2];
    const float* Wk = (const float*)d_in[3];
    const float* bk = (const float*)d_in[4];
    const float* Wv = (const float*)d_in[5];
    const float* bv = (const float*)d_in[6];
    const float* Wo = (const float*)d_in[7];
    const float* bo = (const float*)d_in[8];
    float* out = (float*)d_out;

    cudaFuncSetAttribute(gemm_f16_kernel<1>,
                         cudaFuncAttributeMaxDynamicSharedMemorySize, GEMM_SMEM_BYTES);
    cudaFuncSetAttribute(gemm_f16_kernel<0>,
                         cudaFuncAttributeMaxDynamicSharedMemorySize, GEMM_SMEM_BYTES);
    cudaFuncSetAttribute(flash_attn_kernel,
                         cudaFuncAttributeMaxDynamicSharedMemorySize, FLASH_SMEM_BYTES);

    // 0) fp32 -> fp16 conversions
    {
        int n8x = (MTOT * DM) / 8;          // 1M
        f2h_kernel<<<n8x / 256, 256>>>(x,  0, n8x);
        int n8w = (DM * DM) / 8;            // 128K
        f2h_kernel<<<n8w / 256, 256>>>(Wq, 1, n8w);
        f2h_kernel<<<n8w / 256, 256>>>(Wk, 2, n8w);
        f2h_kernel<<<n8w / 256, 256>>>(Wv, 3, n8w);
        f2h_kernel<<<n8w / 256, 256>>>(Wo, 4, n8w);
    }
    // 1) QKV projections
    {
        dim3 grid(DM / 128, MTOT / 128, 3);
        gemm_f16_kernel<1><<<grid, 256, GEMM_SMEM_BYTES>>>(bq, bk, bv, nullptr);
    }
    // 2) flash attention
    {
        dim3 grid(SS / 128, BB * HEADS);
        flash_attn_kernel<<<grid, 256, FLASH_SMEM_BYTES>>>();
    }
    // 3) output projection
    {
        dim3 grid(DM / 128, MTOT / 128, 1);
        gemm_f16_kernel<0><<<grid, 256, GEMM_SMEM_BYTES>>>(bo, nullptr, nullptr, out);
    }
}

// round 8
// speedup vs baseline: 4.6176x; 1.0226x over previous
#include <cuda_runtime.h>
#include <cuda_fp16.h>
#include <mma.h>
#include <cstdint>

using namespace nvcuda;

// Problem constants
#define DM    1024          // d_model
#define HEADS 16
#define DK    64            // head dim
#define BB    4             // batch
#define SS    2048          // seq len
#define MTOT  (BB * SS)     // 8192 rows

// ---------------------------------------------------------------------------
// Scratch (device globals — no cudaMalloc allowed).
// Only referenced from device code (host-shadow aliasing was the R1 bug).
// NOTE (R7 lesson): tcgen05/TMEM are NOT available — harness PTX target is
// sm_103 (no 'a'), which rejects accelerated features. Legacy HMMA only.
// ---------------------------------------------------------------------------
__device__ __half g_xh[(size_t)MTOT * DM];      // x in fp16
__device__ __half g_Wh[4][(size_t)DM * DM];     // Wq, Wk, Wv, Wo in fp16
__device__ __half g_Qh[(size_t)MTOT * DM];      // (B,H,S,DK)
__device__ __half g_Kh[(size_t)MTOT * DM];      // (B,H,S,DK)
__device__ __half g_Vh[(size_t)MTOT * DM];      // (B,H,S,DK)
__device__ __half g_attnh[(size_t)MTOT * DM];   // (B,S,D)

// ---------------------------------------------------------------------------
// Helpers
// ---------------------------------------------------------------------------
__device__ __forceinline__ uint32_t h2u(__half2 h) {
    return *reinterpret_cast<uint32_t*>(&h);
}

__device__ __forceinline__ void cp_async16(void* smem_ptr, const void* gptr) {
    uint32_t sa = (uint32_t)__cvta_generic_to_shared(smem_ptr);
    asm volatile("cp.async.cg.shared.global [%0], [%1], 16;\n" :: "r"(sa), "l"(gptr));
}
__device__ __forceinline__ void cp_commit() {
    asm volatile("cp.async.commit_group;\n");
}
template <int N>
__device__ __forceinline__ void cp_wait() {
    asm volatile("cp.async.wait_group %0;\n" :: "n"(N));
}

// mma.m16n8k16 fp16: C(16x8,f32) += A(16x16,row) * B(16x8,col)
__device__ __forceinline__ void mma_f16(float c[4], const uint32_t a[4],
                                        uint32_t b0, uint32_t b1) {
    asm volatile(
        "mma.sync.aligned.m16n8k16.row.col.f32.f16.f16.f32 "
        "{%0,%1,%2,%3}, {%4,%5,%6,%7}, {%8,%9}, {%0,%1,%2,%3};"
        : "+f"(c[0]), "+f"(c[1]), "+f"(c[2]), "+f"(c[3])
        : "r"(a[0]), "r"(a[1]), "r"(a[2]), "r"(a[3]), "r"(b0), "r"(b1));
}

// ---------------------------------------------------------------------------
// fp32 -> fp16 conversion. dst_sel: 0 = g_xh, 1..4 = g_Wh[0..3].
// ---------------------------------------------------------------------------
__global__ void f2h_kernel(const float* __restrict__ src, int dst_sel, int n8)
{
    int i = blockIdx.x * blockDim.x + threadIdx.x;
    if (i >= n8) return;
    __half* dst = (dst_sel == 0) ? g_xh : g_Wh[dst_sel - 1];
    const float4* s4 = (const float4*)src;
    float4 v0 = s4[i * 2];
    float4 v1 = s4[i * 2 + 1];
    __half2 h[4];
    h[0] = __floats2half2_rn(v0.x, v0.y);
    h[1] = __floats2half2_rn(v0.z, v0.w);
    h[2] = __floats2half2_rn(v1.x, v1.y);
    h[3] = __floats2half2_rn(v1.z, v1.w);
    *(uint4*)&dst[(size_t)i * 8] = *(uint4*)h;
}

// ---------------------------------------------------------------------------
// GEMM v4 (fp16 in, fp32 acc): C = A @ W + bias. cp.async double-buffered,
// K-tile 64 (4 ks-steps per barrier interval), block tile 128x128, 8 warps
// (warp 32x64, wmma 16x16x16).
// MODE 1: A = g_xh, W = g_Wh[z], C = g_Qh/g_Kh/g_Vh half head-split.
// MODE 0: A = g_attnh, W = g_Wh[3], C = float out (+bias).
// ---------------------------------------------------------------------------
#define KT      64
#define LDA_H   72
#define LDB_H   136
#define A_BUFH  (128 * LDA_H)
#define B_BUFH  (KT * LDB_H)
#define GEMM_SMEM_BYTES ((2 * A_BUFH + 2 * B_BUFH) * (int)sizeof(__half))

template <int MODE>
__global__ __launch_bounds__(256, 2)
void gemm_f16_kernel(const float* __restrict__ b0p,
                     const float* __restrict__ b1p,
                     const float* __restrict__ b2p,
                     float* __restrict__ Cout)
{
    extern __shared__ __half smh[];
    __half* As = smh;                // [2][128][LDA_H]
    __half* Bs = smh + 2 * A_BUFH;   // [2][KT][LDB_H]

    const int z = blockIdx.z;
    const __half* A = (MODE == 0) ? (const __half*)g_attnh : (const __half*)g_xh;
    const __half* W = (MODE == 0) ? g_Wh[3] : g_Wh[z];
    const float* bias = (MODE == 0) ? b0p : (z == 0 ? b0p : (z == 1 ? b1p : b2p));
    __half* Ch = (MODE == 0) ? nullptr : (z == 0 ? g_Qh : (z == 1 ? g_Kh : g_Vh));

    const int tid  = threadIdx.x;
    const int warp = tid >> 5;
    const int lane = tid & 31;
    const int wm   = warp >> 1;
    const int wn   = warp & 1;
    const int m0   = blockIdx.y * 128;
    const int n0   = blockIdx.x * 128;

    auto stage = [&](int buf, int k0) {
        __half* ad = As + buf * A_BUFH;
        __half* bd = Bs + buf * B_BUFH;
#pragma unroll
        for (int t = 0; t < 4; t++) {            // A: 128 rows x 8 chunks = 1024
            int id = tid + t * 256;
            int r = id >> 3, c = (id & 7) * 8;
            cp_async16(&ad[r * LDA_H + c], &A[(size_t)(m0 + r) * DM + k0 + c]);
        }
#pragma unroll
        for (int t = 0; t < 4; t++) {            // B: 64 rows x 16 chunks = 1024
            int id = tid + t * 256;
            int r = id >> 4, c = (id & 15) * 8;
            cp_async16(&bd[r * LDB_H + c], &W[(size_t)(k0 + r) * DM + n0 + c]);
        }
        cp_commit();
    };

    wmma::fragment<wmma::accumulator, 16, 16, 16, float> acc[2][4];
#pragma unroll
    for (int im = 0; im < 2; im++)
#pragma unroll
        for (int in = 0; in < 4; in++)
            wmma::fill_fragment(acc[im][in], 0.0f);

    stage(0, 0);

    const int NT = DM / KT;   // 16
    for (int t = 0; t < NT; t++) {
        int buf = t & 1;
        if (t + 1 < NT) {
            stage(buf ^ 1, (t + 1) * KT);
            cp_wait<1>();
        } else {
            cp_wait<0>();
        }
        __syncthreads();

        const __half* av = As + buf * A_BUFH;
        const __half* bv = Bs + buf * B_BUFH;
#pragma unroll
        for (int ks = 0; ks < 4; ks++) {
            wmma::fragment<wmma::matrix_a, 16, 16, 16, __half, wmma::row_major> af[2];
            wmma::fragment<wmma::matrix_b, 16, 16, 16, __half, wmma::row_major> bf[4];
#pragma unroll
            for (int im = 0; im < 2; im++)
                wmma::load_matrix_sync(af[im], &av[(wm * 32 + im * 16) * LDA_H + ks * 16], LDA_H);
#pragma unroll
            for (int in = 0; in < 4; in++)
                wmma::load_matrix_sync(bf[in], &bv[(ks * 16) * LDB_H + wn * 64 + in * 16], LDB_H);
#pragma unroll
            for (int im = 0; im < 2; im++)
#pragma unroll
                for (int in = 0; in < 4; in++)
                    wmma::mma_sync(acc[im][in], af[im], bf[in], acc[im][in]);
        }
        __syncthreads();
    }

    // --- epilogue: frag -> smem (aliases As) -> global (+bias, layout map) ---
    float* epi = (float*)smh + warp * 256;
#pragma unroll
    for (int im = 0; im < 2; im++) {
#pragma unroll
        for (int in = 0; in < 4; in++) {
            wmma::store_matrix_sync(epi, acc[im][in], 16, wmma::mem_row_major);
            __syncwarp();
#pragma unroll
            for (int i = 0; i < 8; i++) {
                int v = lane * 8 + i;
                int r = v >> 4, c = v & 15;
                int gm = m0 + wm * 32 + im * 16 + r;
                int gn = n0 + wn * 64 + in * 16 + c;
                float val = epi[v] + bias[gn];
                if (MODE == 0) {
                    Cout[(size_t)gm * DM + gn] = val;
                } else {
                    int b = gm >> 11, s = gm & 2047;
                    int h = gn >> 6,  d = gn & 63;
                    Ch[(((size_t)(b * HEADS + h)) * SS + s) * DK + d] = __float2half_rn(val);
                }
            }
            __syncwarp();
        }
    }
}

// ---------------------------------------------------------------------------
// Flash attention (unchanged from R6 — known good, ~250us)
// ---------------------------------------------------------------------------
#define LDH 72
#define FLASH_SMEM_BYTES (2 * 64 * LDH * (int)sizeof(__half))

__global__ __launch_bounds__(256, 2)
void flash_attn_kernel()
{
    extern __shared__ __half smf[];
    __half* Ks  = smf;             // [64 keys][LDH]
    __half* VsT = smf + 64 * LDH;  // [64 dk][LDH] (key-contiguous rows)

    const int tid  = threadIdx.x;
    const int warp = tid >> 5;
    const int lane = tid & 31;
    const int gr   = lane >> 2;
    const int gc   = lane & 3;
    const int qt   = blockIdx.x;
    const int bh   = blockIdx.y;

    const __half* Qb = g_Qh + (size_t)bh * SS * DK;
    const __half* Kb = g_Kh + (size_t)bh * SS * DK;
    const __half* Vb = g_Vh + (size_t)bh * SS * DK;

    const int qrow = qt * 128 + warp * 16;

    const __half2 sc2 = __float2half2_rn(0.125f);
    uint32_t qa[4][4];
#pragma unroll
    for (int kk = 0; kk < 4; kk++) {
        const __half* q0 = Qb + (size_t)(qrow + gr)     * DK + kk * 16 + 2 * gc;
        const __half* q1 = Qb + (size_t)(qrow + gr + 8) * DK + kk * 16 + 2 * gc;
        qa[kk][0] = h2u(__hmul2(*(const __half2*)(q0),     sc2));
        qa[kk][1] = h2u(__hmul2(*(const __half2*)(q1),     sc2));
        qa[kk][2] = h2u(__hmul2(*(const __half2*)(q0 + 8), sc2));
        qa[kk][3] = h2u(__hmul2(*(const __half2*)(q1 + 8), sc2));
    }

    float o[8][4];
#pragma unroll
    for (int nt = 0; nt < 8; nt++) { o[nt][0] = o[nt][1] = o[nt][2] = o[nt][3] = 0.0f; }
    float m0 = -1e30f, m1 = -1e30f, l0 = 0.0f, l1 = 0.0f;

    for (int jt = 0; jt < SS / 64; jt++) {
        const __half* Kt = Kb + (size_t)(jt * 64) * DK;
        const __half* Vt = Vb + (size_t)(jt * 64) * DK;
#pragma unroll
        for (int rep = 0; rep < 2; rep++) {
            int id  = tid + rep * 256;
            int key = id >> 3;
            int c8  = (id & 7) * 8;
            uint4 kraw = *(const uint4*)&Kt[(size_t)key * DK + c8];
            *(uint4*)&Ks[key * LDH + c8] = kraw;
            uint4 vraw = *(const uint4*)&Vt[(size_t)key * DK + c8];
            const __half* vh = (const __half*)&vraw;
#pragma unroll
            for (int j = 0; j < 8; j++)
                VsT[(c8 + j) * LDH + key] = vh[j];
        }
        __syncthreads();

        float s[8][4];
#pragma unroll
        for (int nt = 0; nt < 8; nt++) { s[nt][0] = s[nt][1] = s[nt][2] = s[nt][3] = 0.0f; }
#pragma unroll
        for (int kk = 0; kk < 4; kk++) {
#pragma unroll
            for (int nt = 0; nt < 8; nt++) {
                const __half* kb = &Ks[(nt * 8 + gr) * LDH + kk * 16 + 2 * gc];
                uint32_t b0 = h2u(*(const __half2*)(kb));
                uint32_t b1 = h2u(*(const __half2*)(kb + 8));
                mma_f16(s[nt], qa[kk], b0, b1);
            }
        }

        float mx0 = -1e30f, mx1 = -1e30f;
#pragma unroll
        for (int nt = 0; nt < 8; nt++) {
            mx0 = fmaxf(mx0, fmaxf(s[nt][0], s[nt][1]));
            mx1 = fmaxf(mx1, fmaxf(s[nt][2], s[nt][3]));
        }
        mx0 = fmaxf(mx0, __shfl_xor_sync(0xffffffffu, mx0, 1));
        mx0 = fmaxf(mx0, __shfl_xor_sync(0xffffffffu, mx0, 2));
        mx1 = fmaxf(mx1, __shfl_xor_sync(0xffffffffu, mx1, 1));
        mx1 = fmaxf(mx1, __shfl_xor_sync(0xffffffffu, mx1, 2));

        float mn0 = fmaxf(m0, mx0), mn1 = fmaxf(m1, mx1);
        float sc0 = __expf(m0 - mn0), sc1 = __expf(m1 - mn1);
        float sum0 = 0.0f, sum1 = 0.0f;
#pragma unroll
        for (int nt = 0; nt < 8; nt++) {
            s[nt][0] = __expf(s[nt][0] - mn0);
            s[nt][1] = __expf(s[nt][1] - mn0);
            s[nt][2] = __expf(s[nt][2] - mn1);
            s[nt][3] = __expf(s[nt][3] - mn1);
            sum0 += s[nt][0] + s[nt][1];
            sum1 += s[nt][2] + s[nt][3];
        }
        sum0 += __shfl_xor_sync(0xffffffffu, sum0, 1);
        sum0 += __shfl_xor_sync(0xffffffffu, sum0, 2);
        sum1 += __shfl_xor_sync(0xffffffffu, sum1, 1);
        sum1 += __shfl_xor_sync(0xffffffffu, sum1, 2);
        l0 = l0 * sc0 + sum0;
        l1 = l1 * sc1 + sum1;
        m0 = mn0; m1 = mn1;

#pragma unroll
        for (int nt = 0; nt < 8; nt++) {
            o[nt][0] *= sc0; o[nt][1] *= sc0;
            o[nt][2] *= sc1; o[nt][3] *= sc1;
        }

#pragma unroll
        for (int t = 0; t < 4; t++) {
            uint32_t pa[4];
            pa[0] = h2u(__floats2half2_rn(s[2 * t][0],     s[2 * t][1]));
            pa[1] = h2u(__floats2half2_rn(s[2 * t][2],     s[2 * t][3]));
            pa[2] = h2u(__floats2half2_rn(s[2 * t + 1][0], s[2 * t + 1][1]));
            pa[3] = h2u(__floats2half2_rn(s[2 * t + 1][2], s[2 * t + 1][3]));
#pragma unroll
            for (int nt = 0; nt < 8; nt++) {
                const __half* vb = &VsT[(nt * 8 + gr) * LDH + t * 16 + 2 * gc];
                uint32_t b0 = h2u(*(const __half2*)(vb));
                uint32_t b1 = h2u(*(const __half2*)(vb + 8));
                mma_f16(o[nt], pa, b0, b1);
            }
        }
        __syncthreads();
    }

    {
        int b = bh >> 4, h = bh & 15;
        float inv0 = 1.0f / l0, inv1 = 1.0f / l1;
        __half* out0 = g_attnh + ((size_t)(b * SS + qrow + gr))     * DM + h * DK;
        __half* out1 = g_attnh + ((size_t)(b * SS + qrow + gr + 8)) * DM + h * DK;
#pragma unroll
        for (int nt = 0; nt < 8; nt++) {
            *(__half2*)&out0[nt * 8 + gc * 2] = __floats2half2_rn(o[nt][0] * inv0, o[nt][1] * inv0);
            *(__half2*)&out1[nt * 8 + gc * 2] = __floats2half2_rn(o[nt][2] * inv1, o[nt][3] * inv1);
        }
    }
}

// ---------------------------------------------------------------------------
// Launcher. Inputs (metadata order): x, Wq, bq, Wk, bk, Wv, bv, Wo, bo
// ---------------------------------------------------------------------------
extern "C" void kernel_launch(void* const* d_in, const int* in_sizes, int n_in,
                              void* d_out, int out_size)
{
    const float* x  = (const float*)d_in[0];
    const float* Wq = (const float*)d_in[1];
    const float* bq = (const float*)d_in[2];
    const float* Wk = (const float*)d_in[3];
    const float* bk = (const float*)d_in[4];
    const float* Wv = (const float*)d_in[5];
    const float* bv = (const float*)d_in[6];
    const float* Wo = (const float*)d_in[7];
    const float* bo = (const float*)d_in[8];
    float* out = (float*)d_out;

    cudaFuncSetAttribute(gemm_f16_kernel<1>,
                         cudaFuncAttributeMaxDynamicSharedMemorySize, GEMM_SMEM_BYTES);
    cudaFuncSetAttribute(gemm_f16_kernel<0>,
                         cudaFuncAttributeMaxDynamicSharedMemorySize, GEMM_SMEM_BYTES);
    cudaFuncSetAttribute(flash_attn_kernel,
                         cudaFuncAttributeMaxDynamicSharedMemorySize, FLASH_SMEM_BYTES);

    // 0) fp32 -> fp16 conversions
    {
        int n8x = (MTOT * DM) / 8;          // 1M
        f2h_kernel<<<n8x / 256, 256>>>(x,  0, n8x);
        int n8w = (DM * DM) / 8;            // 128K
        f2h_kernel<<<n8w / 256, 256>>>(Wq, 1, n8w);
        f2h_kernel<<<n8w / 256, 256>>>(Wk, 2, n8w);
        f2h_kernel<<<n8w / 256, 256>>>(Wv, 3, n8w);
        f2h_kernel<<<n8w / 256, 256>>>(Wo, 4, n8w);
    }
    // 1) QKV projections
    {
        dim3 grid(DM / 128, MTOT / 128, 3);
        gemm_f16_kernel<1><<<grid, 256, GEMM_SMEM_BYTES>>>(bq, bk, bv, nullptr);
    }
    // 2) flash attention
    {
        dim3 grid(SS / 128, BB * HEADS);
        flash_attn_kernel<<<grid, 256, FLASH_SMEM_BYTES>>>();
    }
    // 3) output projection
    {
        dim3 grid(DM / 128, MTOT / 128, 1);
        gemm_f16_kernel<0><<<grid, 256, GEMM_SMEM_BYTES>>>(bo, nullptr, nullptr, out);
    }
}